// round 1
// baseline (speedup 1.0000x reference)
#include <cuda_runtime.h>

#define DIMV   768
#define QKV3   2304
#define BATCH  8
#define SEQT   1024
#define NHEAD  12
#define HDIM   64
#define MROWS  (BATCH * SEQT)   // 8192

// Scratch (static device globals — allowed; no runtime allocation)
__device__ float g_qkv[(size_t)MROWS * QKV3];   // ~75.5 MB
__device__ float g_y[(size_t)MROWS * DIMV];     // ~25 MB

// ---------------------------------------------------------------------------
// SGEMM: C[M,N] = A[M,K] @ B[K,N] + bias[N]
// 128x128 block tile, BK=8, 256 threads, 8x8 per-thread register tile.
// M % 128 == 0, N % 128 == 0, K % 8 == 0 guaranteed by problem shapes.
// ---------------------------------------------------------------------------
__global__ __launch_bounds__(256, 2)
void sgemm_bias_kernel(const float* __restrict__ A,
                       const float* __restrict__ Bm,
                       const float* __restrict__ bias,
                       float* __restrict__ C,
                       int M, int N, int K)
{
    const int BM = 128, BN = 128, BK = 8;
    __shared__ float As[BK][BM];
    __shared__ float Bs[BK][BN];

    int tid = threadIdx.x;
    int tx = tid & 15;         // 0..15 -> col group
    int ty = tid >> 4;         // 0..15 -> row group
    int m0 = blockIdx.y * BM;
    int n0 = blockIdx.x * BN;

    // A-tile load mapping: one float4 per thread
    int arow = tid >> 1;            // 0..127
    int ac4  = (tid & 1) * 4;       // 0 or 4
    // B-tile load mapping: one float4 per thread
    int brow = tid >> 5;            // 0..7
    int bc4  = (tid & 31) * 4;      // 0..124

    const float* Aptr = A + (size_t)(m0 + arow) * K + ac4;
    const float* Bptr = Bm + (size_t)brow * N + n0 + bc4;

    float acc[8][8];
    #pragma unroll
    for (int i = 0; i < 8; i++)
        #pragma unroll
        for (int j = 0; j < 8; j++) acc[i][j] = 0.f;

    for (int k0 = 0; k0 < K; k0 += BK) {
        float4 av = *(const float4*)(Aptr + k0);
        As[ac4 + 0][arow] = av.x;
        As[ac4 + 1][arow] = av.y;
        As[ac4 + 2][arow] = av.z;
        As[ac4 + 3][arow] = av.w;
        *(float4*)&Bs[brow][bc4] = *(const float4*)(Bptr + (size_t)k0 * N);
        __syncthreads();

        #pragma unroll
        for (int kk = 0; kk < BK; kk++) {
            float a[8], b[8];
            *(float4*)(a)     = *(float4*)&As[kk][ty * 8];
            *(float4*)(a + 4) = *(float4*)&As[kk][ty * 8 + 4];
            *(float4*)(b)     = *(float4*)&Bs[kk][tx * 8];
            *(float4*)(b + 4) = *(float4*)&Bs[kk][tx * 8 + 4];
            #pragma unroll
            for (int i = 0; i < 8; i++)
                #pragma unroll
                for (int j = 0; j < 8; j++)
                    acc[i][j] = fmaf(a[i], b[j], acc[i][j]);
        }
        __syncthreads();
    }

    float bb[8];
    *(float4*)(bb)     = *(const float4*)&bias[n0 + tx * 8];
    *(float4*)(bb + 4) = *(const float4*)&bias[n0 + tx * 8 + 4];

    #pragma unroll
    for (int i = 0; i < 8; i++) {
        float* cp = C + (size_t)(m0 + ty * 8 + i) * N + n0 + tx * 8;
        float4 v0, v1;
        v0.x = acc[i][0] + bb[0]; v0.y = acc[i][1] + bb[1];
        v0.z = acc[i][2] + bb[2]; v0.w = acc[i][3] + bb[3];
        v1.x = acc[i][4] + bb[4]; v1.y = acc[i][5] + bb[5];
        v1.z = acc[i][6] + bb[6]; v1.w = acc[i][7] + bb[7];
        *(float4*)(cp)     = v0;
        *(float4*)(cp + 4) = v1;
    }
}

// ---------------------------------------------------------------------------
// Flash attention: one block = (32 queries) x (one head) x (one batch).
// Streams K/V in tiles of 64 rows with online softmax.
// Thread layout (256 threads): qr = tid/8 (query row), g8 = tid%8.
//   - score phase: thread owns 8 key columns kkb = g8*8 .. +8
//   - accum phase: thread owns 8 hd columns  c0  = g8*8 .. +8
// ---------------------------------------------------------------------------
#define BQ   32
#define BKV  64
#define KP   68   // smem pitch for K/V/S tiles (bank-conflict padding)

__global__ __launch_bounds__(256)
void flash_attn_kernel(const float* __restrict__ qkv, float* __restrict__ y)
{
    extern __shared__ float sm[];
    float* Qs = sm;                       // BQ  * HDIM  = 2048
    float* Ks = Qs + BQ * HDIM;           // BKV * KP    = 4352
    float* Vs = Ks + BKV * KP;            // BKV * KP    = 4352
    float* S  = Vs + BKV * KP;            // BQ  * KP    = 2176
    float* PM = S + BQ * KP;              // 256
    float* PS = PM + 256;                 // 256

    int tid = threadIdx.x;
    int q0  = blockIdx.x * BQ;
    int h   = blockIdx.y;
    int b   = blockIdx.z;
    const float scale = 0.125f;           // 1/sqrt(64)

    size_t base = (size_t)b * SEQT * QKV3;
    int qoff = h * HDIM;
    int koff = DIMV + h * HDIM;
    int voff = 2 * DIMV + h * HDIM;

    // Load Q tile (2 float4 per thread)
    for (int i = tid; i < BQ * HDIM / 4; i += 256) {
        int r = i / (HDIM / 4);
        int c = (i % (HDIM / 4)) * 4;
        *(float4*)&Qs[r * HDIM + c] =
            *(const float4*)&qkv[base + (size_t)(q0 + r) * QKV3 + qoff + c];
    }

    int qr  = tid >> 3;       // 0..31
    int g8  = tid & 7;        // 0..7
    int kkb = g8 * 8;
    int c0  = g8 * 8;

    float m_prev = -1e30f;
    float l = 0.f;
    float acc[8];
    #pragma unroll
    for (int j = 0; j < 8; j++) acc[j] = 0.f;

    for (int kv0 = 0; kv0 < SEQT; kv0 += BKV) {
        __syncthreads();  // protect Ks/Vs/S from previous iteration consumers
        for (int i = tid; i < BKV * HDIM / 4; i += 256) {
            int r = i / (HDIM / 4);
            int c = (i % (HDIM / 4)) * 4;
            size_t row = base + (size_t)(kv0 + r) * QKV3;
            *(float4*)&Ks[r * KP + c] = *(const float4*)&qkv[row + koff + c];
            *(float4*)&Vs[r * KP + c] = *(const float4*)&qkv[row + voff + c];
        }
        __syncthreads();

        // Scores: S[qr][kkb..kkb+8) = Q[qr] . K[kk]
        float sc[8];
        #pragma unroll
        for (int j = 0; j < 8; j++) sc[j] = 0.f;
        #pragma unroll 4
        for (int d = 0; d < HDIM; d += 4) {
            float4 qv = *(float4*)&Qs[qr * HDIM + d];
            #pragma unroll
            for (int j = 0; j < 8; j++) {
                float4 kv = *(float4*)&Ks[(kkb + j) * KP + d];
                sc[j] = fmaf(qv.x, kv.x, sc[j]);
                sc[j] = fmaf(qv.y, kv.y, sc[j]);
                sc[j] = fmaf(qv.z, kv.z, sc[j]);
                sc[j] = fmaf(qv.w, kv.w, sc[j]);
            }
        }
        float pm = -1e30f;
        #pragma unroll
        for (int j = 0; j < 8; j++) {
            sc[j] *= scale;
            pm = fmaxf(pm, sc[j]);
        }
        PM[qr * 8 + g8] = pm;
        __syncthreads();

        float m_tile = PM[qr * 8];
        #pragma unroll
        for (int j = 1; j < 8; j++) m_tile = fmaxf(m_tile, PM[qr * 8 + j]);
        float m_new = fmaxf(m_prev, m_tile);

        float ps = 0.f;
        #pragma unroll
        for (int j = 0; j < 8; j++) {
            float p = __expf(sc[j] - m_new);
            S[qr * KP + kkb + j] = p;
            ps += p;
        }
        PS[qr * 8 + g8] = ps;
        __syncthreads();

        float rs = 0.f;
        #pragma unroll
        for (int j = 0; j < 8; j++) rs += PS[qr * 8 + j];
        float corr = __expf(m_prev - m_new);
        l = l * corr + rs;
        m_prev = m_new;
        #pragma unroll
        for (int j = 0; j < 8; j++) acc[j] *= corr;

        // acc += P @ V  (thread owns hd columns c0..c0+8 of row qr)
        #pragma unroll 8
        for (int kk = 0; kk < BKV; kk++) {
            float p = S[qr * KP + kk];
            float4 v0 = *(float4*)&Vs[kk * KP + c0];
            float4 v1 = *(float4*)&Vs[kk * KP + c0 + 4];
            acc[0] = fmaf(p, v0.x, acc[0]);
            acc[1] = fmaf(p, v0.y, acc[1]);
            acc[2] = fmaf(p, v0.z, acc[2]);
            acc[3] = fmaf(p, v0.w, acc[3]);
            acc[4] = fmaf(p, v1.x, acc[4]);
            acc[5] = fmaf(p, v1.y, acc[5]);
            acc[6] = fmaf(p, v1.z, acc[6]);
            acc[7] = fmaf(p, v1.w, acc[7]);
        }
    }

    float inv = 1.f / l;
    float* outp = &y[(size_t)(b * SEQT + q0 + qr) * DIMV + h * HDIM + c0];
    float4 o0, o1;
    o0.x = acc[0] * inv; o0.y = acc[1] * inv; o0.z = acc[2] * inv; o0.w = acc[3] * inv;
    o1.x = acc[4] * inv; o1.y = acc[5] * inv; o1.z = acc[6] * inv; o1.w = acc[7] * inv;
    *(float4*)(outp)     = o0;
    *(float4*)(outp + 4) = o1;
}

// ---------------------------------------------------------------------------
extern "C" void kernel_launch(void* const* d_in, const int* in_sizes, int n_in,
                              void* d_out, int out_size)
{
    const float* x      = (const float*)d_in[0];  // [8,1024,768]
    const float* W_qkv  = (const float*)d_in[1];  // [768,2304]
    const float* b_qkv  = (const float*)d_in[2];  // [2304]
    const float* W_proj = (const float*)d_in[3];  // [768,768]
    const float* b_proj = (const float*)d_in[4];  // [768]
    float* out = (float*)d_out;                   // [8,1024,768]

    float* qkv;
    float* yb;
    cudaGetSymbolAddress((void**)&qkv, g_qkv);
    cudaGetSymbolAddress((void**)&yb, g_y);

    // 1) QKV projection: [8192,768] @ [768,2304] + bias
    {
        dim3 grid(QKV3 / 128, MROWS / 128);
        sgemm_bias_kernel<<<grid, 256>>>(x, W_qkv, b_qkv, qkv, MROWS, QKV3, DIMV);
    }

    // 2) Flash attention
    {
        int smem_bytes = (BQ * HDIM + 2 * BKV * KP + BQ * KP + 512) * (int)sizeof(float);
        cudaFuncSetAttribute(flash_attn_kernel,
                             cudaFuncAttributeMaxDynamicSharedMemorySize, smem_bytes);
        dim3 grid(SEQT / BQ, NHEAD, BATCH);
        flash_attn_kernel<<<grid, 256, smem_bytes>>>(qkv, yb);
    }

    // 3) Output projection: [8192,768] @ [768,768] + bias
    {
        dim3 grid(DIMV / 128, MROWS / 128);
        sgemm_bias_kernel<<<grid, 256>>>(yb, W_proj, b_proj, out, MROWS, DIMV, DIMV);
    }
}

// round 2
// speedup vs baseline: 2.8520x; 2.8520x over previous
#include <cuda_runtime.h>

#define DIMV   768
#define QKV3   2304
#define BATCH  8
#define SEQT   1024
#define NHEAD  12
#define HDIM   64
#define MROWS  (BATCH * SEQT)   // 8192

__device__ float g_qkv[(size_t)MROWS * QKV3];   // ~75.5 MB
__device__ float g_y[(size_t)MROWS * DIMV];     // ~25 MB

// ---------------------------------------------------------------------------
// SGEMM: C[M,N] = A[M,K] @ B[K,N] + bias[N]  (unchanged from R1)
// ---------------------------------------------------------------------------
__global__ __launch_bounds__(256, 2)
void sgemm_bias_kernel(const float* __restrict__ A,
                       const float* __restrict__ Bm,
                       const float* __restrict__ bias,
                       float* __restrict__ C,
                       int M, int N, int K)
{
    const int BM = 128, BN = 128, BK = 8;
    __shared__ float As[BK][BM];
    __shared__ float Bs[BK][BN];

    int tid = threadIdx.x;
    int tx = tid & 15;
    int ty = tid >> 4;
    int m0 = blockIdx.y * BM;
    int n0 = blockIdx.x * BN;

    int arow = tid >> 1;
    int ac4  = (tid & 1) * 4;
    int brow = tid >> 5;
    int bc4  = (tid & 31) * 4;

    const float* Aptr = A + (size_t)(m0 + arow) * K + ac4;
    const float* Bptr = Bm + (size_t)brow * N + n0 + bc4;

    float acc[8][8];
    #pragma unroll
    for (int i = 0; i < 8; i++)
        #pragma unroll
        for (int j = 0; j < 8; j++) acc[i][j] = 0.f;

    for (int k0 = 0; k0 < K; k0 += BK) {
        float4 av = *(const float4*)(Aptr + k0);
        As[ac4 + 0][arow] = av.x;
        As[ac4 + 1][arow] = av.y;
        As[ac4 + 2][arow] = av.z;
        As[ac4 + 3][arow] = av.w;
        *(float4*)&Bs[brow][bc4] = *(const float4*)(Bptr + (size_t)k0 * N);
        __syncthreads();

        #pragma unroll
        for (int kk = 0; kk < BK; kk++) {
            float a[8], b[8];
            *(float4*)(a)     = *(float4*)&As[kk][ty * 8];
            *(float4*)(a + 4) = *(float4*)&As[kk][ty * 8 + 4];
            *(float4*)(b)     = *(float4*)&Bs[kk][tx * 8];
            *(float4*)(b + 4) = *(float4*)&Bs[kk][tx * 8 + 4];
            #pragma unroll
            for (int i = 0; i < 8; i++)
                #pragma unroll
                for (int j = 0; j < 8; j++)
                    acc[i][j] = fmaf(a[i], b[j], acc[i][j]);
        }
        __syncthreads();
    }

    float bb[8];
    *(float4*)(bb)     = *(const float4*)&bias[n0 + tx * 8];
    *(float4*)(bb + 4) = *(const float4*)&bias[n0 + tx * 8 + 4];

    #pragma unroll
    for (int i = 0; i < 8; i++) {
        float* cp = C + (size_t)(m0 + ty * 8 + i) * N + n0 + tx * 8;
        float4 v0, v1;
        v0.x = acc[i][0] + bb[0]; v0.y = acc[i][1] + bb[1];
        v0.z = acc[i][2] + bb[2]; v0.w = acc[i][3] + bb[3];
        v1.x = acc[i][4] + bb[4]; v1.y = acc[i][5] + bb[5];
        v1.z = acc[i][6] + bb[6]; v1.w = acc[i][7] + bb[7];
        *(float4*)(cp)     = v0;
        *(float4*)(cp + 4) = v1;
    }
}

// ---------------------------------------------------------------------------
// Flash attention, register-tiled.
// Block = 128 queries x one (batch, head). KV streamed in tiles of 128.
// 256 threads as 16x16 grid:
//   QK phase: thread (ty,tx) owns 8x8 score block; operands from transposed
//             Qt[d][q], Kt[d][k] smem tiles -> conflict-free LDS.128.
//   PV phase: thread (ty,tx) owns 8 rows x 4 hd-cols accumulator.
// Row softmax stats reduced via shfl within the 16-lane row group.
// ---------------------------------------------------------------------------
#define BQ   128
#define BKV  128
#define TPITCH 132   // pitch for transposed Qt/Kt and for S

__global__ __launch_bounds__(256)
void flash_attn_kernel(const float* __restrict__ qkv, float* __restrict__ y)
{
    extern __shared__ float sm[];
    float* Qt = sm;                         // 64 * 132 = 8448
    float* Kt = Qt + HDIM * TPITCH;         // 64 * 132 = 8448
    float* Vs = Kt + HDIM * TPITCH;         // 128 * 64 = 8192
    float* S  = Vs + BKV * HDIM;            // 128 * 132 = 16896

    int tid = threadIdx.x;
    int ty  = tid >> 4;      // 0..15 row group (8 rows)
    int tx  = tid & 15;      // 0..15 col group
    int q0  = blockIdx.x * BQ;
    int h   = blockIdx.y;
    int b   = blockIdx.z;
    const float scale = 0.125f;

    size_t base = (size_t)b * SEQT * QKV3;
    int qoff = h * HDIM;
    int koff = DIMV + h * HDIM;
    int voff = 2 * DIMV + h * HDIM;

    // Load Q tile transposed: Qt[d][q]
    #pragma unroll
    for (int it = 0; it < 8; it++) {
        int idx = tid + it * 256;           // 0..2047
        int q  = idx >> 4;
        int dc = (idx & 15) * 4;
        float4 v = *(const float4*)&qkv[base + (size_t)(q0 + q) * QKV3 + qoff + dc];
        Qt[(dc + 0) * TPITCH + q] = v.x;
        Qt[(dc + 1) * TPITCH + q] = v.y;
        Qt[(dc + 2) * TPITCH + q] = v.z;
        Qt[(dc + 3) * TPITCH + q] = v.w;
    }

    float m_run[8], l_run[8], o[8][4];
    #pragma unroll
    for (int i = 0; i < 8; i++) {
        m_run[i] = -1e30f;
        l_run[i] = 0.f;
        #pragma unroll
        for (int c = 0; c < 4; c++) o[i][c] = 0.f;
    }

    for (int kv0 = 0; kv0 < SEQT; kv0 += BKV) {
        __syncthreads();   // protect Kt/Vs (prev QK/PV readers done)
        // Load K transposed + V natural
        #pragma unroll
        for (int it = 0; it < 8; it++) {
            int idx = tid + it * 256;
            int k  = idx >> 4;
            int dc = (idx & 15) * 4;
            size_t row = base + (size_t)(kv0 + k) * QKV3;
            float4 kv = *(const float4*)&qkv[row + koff + dc];
            Kt[(dc + 0) * TPITCH + k] = kv.x;
            Kt[(dc + 1) * TPITCH + k] = kv.y;
            Kt[(dc + 2) * TPITCH + k] = kv.z;
            Kt[(dc + 3) * TPITCH + k] = kv.w;
            *(float4*)&Vs[k * HDIM + dc] = *(const float4*)&qkv[row + voff + dc];
        }
        __syncthreads();

        // ---- QK: s[8][8] = Q(8 rows) . K(8 cols) ----
        float s[8][8];
        #pragma unroll
        for (int i = 0; i < 8; i++)
            #pragma unroll
            for (int j = 0; j < 8; j++) s[i][j] = 0.f;

        #pragma unroll 8
        for (int d = 0; d < HDIM; d++) {
            float a[8], bb[8];
            *(float4*)(a)      = *(float4*)&Qt[d * TPITCH + ty * 8];
            *(float4*)(a + 4)  = *(float4*)&Qt[d * TPITCH + ty * 8 + 4];
            *(float4*)(bb)     = *(float4*)&Kt[d * TPITCH + tx * 8];
            *(float4*)(bb + 4) = *(float4*)&Kt[d * TPITCH + tx * 8 + 4];
            #pragma unroll
            for (int i = 0; i < 8; i++)
                #pragma unroll
                for (int j = 0; j < 8; j++)
                    s[i][j] = fmaf(a[i], bb[j], s[i][j]);
        }

        // ---- softmax (online) per row ----
        #pragma unroll
        for (int i = 0; i < 8; i++) {
            float mx = -1e30f;
            #pragma unroll
            for (int j = 0; j < 8; j++) {
                s[i][j] *= scale;
                mx = fmaxf(mx, s[i][j]);
            }
            // reduce max over the 16 threads of this row group
            #pragma unroll
            for (int msk = 1; msk < 16; msk <<= 1)
                mx = fmaxf(mx, __shfl_xor_sync(0xffffffffu, mx, msk));
            float m_new = fmaxf(m_run[i], mx);
            float corr = __expf(m_run[i] - m_new);
            float rs = 0.f;
            #pragma unroll
            for (int j = 0; j < 8; j++) {
                float p = __expf(s[i][j] - m_new);
                s[i][j] = p;
                rs += p;
            }
            #pragma unroll
            for (int msk = 1; msk < 16; msk <<= 1)
                rs += __shfl_xor_sync(0xffffffffu, rs, msk);
            l_run[i] = l_run[i] * corr + rs;
            m_run[i] = m_new;
            #pragma unroll
            for (int c = 0; c < 4; c++) o[i][c] *= corr;
            // store P row block (conflict-free STS.128)
            float* sp = &S[(ty * 8 + i) * TPITCH + tx * 8];
            *(float4*)(sp)     = make_float4(s[i][0], s[i][1], s[i][2], s[i][3]);
            *(float4*)(sp + 4) = make_float4(s[i][4], s[i][5], s[i][6], s[i][7]);
        }
        __syncthreads();

        // ---- PV: o[8][4] += P(8 rows) @ V(4 cols) ----
        int c0 = tx * 4;
        #pragma unroll 4
        for (int k = 0; k < BKV; k++) {
            float4 v = *(float4*)&Vs[k * HDIM + c0];
            #pragma unroll
            for (int i = 0; i < 8; i++) {
                float p = S[(ty * 8 + i) * TPITCH + k];
                o[i][0] = fmaf(p, v.x, o[i][0]);
                o[i][1] = fmaf(p, v.y, o[i][1]);
                o[i][2] = fmaf(p, v.z, o[i][2]);
                o[i][3] = fmaf(p, v.w, o[i][3]);
            }
        }
    }

    // Epilogue
    #pragma unroll
    for (int i = 0; i < 8; i++) {
        float inv = 1.f / l_run[i];
        int row = q0 + ty * 8 + i;
        float4 r;
        r.x = o[i][0] * inv; r.y = o[i][1] * inv;
        r.z = o[i][2] * inv; r.w = o[i][3] * inv;
        *(float4*)&y[(size_t)(b * SEQT + row) * DIMV + h * HDIM + tx * 4] = r;
    }
}

// ---------------------------------------------------------------------------
extern "C" void kernel_launch(void* const* d_in, const int* in_sizes, int n_in,
                              void* d_out, int out_size)
{
    const float* x      = (const float*)d_in[0];
    const float* W_qkv  = (const float*)d_in[1];
    const float* b_qkv  = (const float*)d_in[2];
    const float* W_proj = (const float*)d_in[3];
    const float* b_proj = (const float*)d_in[4];
    float* out = (float*)d_out;

    float* qkv;
    float* yb;
    cudaGetSymbolAddress((void**)&qkv, g_qkv);
    cudaGetSymbolAddress((void**)&yb, g_y);

    // 1) QKV projection
    {
        dim3 grid(QKV3 / 128, MROWS / 128);
        sgemm_bias_kernel<<<grid, 256>>>(x, W_qkv, b_qkv, qkv, MROWS, QKV3, DIMV);
    }

    // 2) Flash attention
    {
        int smem_bytes = (2 * HDIM * TPITCH + BKV * HDIM + BQ * TPITCH) * (int)sizeof(float);
        cudaFuncSetAttribute(flash_attn_kernel,
                             cudaFuncAttributeMaxDynamicSharedMemorySize, smem_bytes);
        dim3 grid(SEQT / BQ, NHEAD, BATCH);
        flash_attn_kernel<<<grid, 256, smem_bytes>>>(qkv, yb);
    }

    // 3) Output projection
    {
        dim3 grid(DIMV / 128, MROWS / 128);
        sgemm_bias_kernel<<<grid, 256>>>(yb, W_proj, b_proj, out, MROWS, DIMV, DIMV);
    }
}

// round 3
// speedup vs baseline: 5.9808x; 2.0970x over previous
#include <cuda_runtime.h>
#include <cstdint>

#define DIMV   768
#define QKV3   2304
#define BATCH  8
#define SEQT   1024
#define NHEAD  12
#define HDIM   64
#define MROWS  (BATCH * SEQT)   // 8192

__device__ float g_qkv[(size_t)MROWS * QKV3];   // ~75.5 MB
__device__ float g_y[(size_t)MROWS * DIMV];     // ~25 MB

// ---------------------------------------------------------------------------
// SGEMM: C[M,N] = A[M,K] @ B[K,N] + bias[N]  (fp32, unchanged)
// ---------------------------------------------------------------------------
__global__ __launch_bounds__(256, 2)
void sgemm_bias_kernel(const float* __restrict__ A,
                       const float* __restrict__ Bm,
                       const float* __restrict__ bias,
                       float* __restrict__ C,
                       int M, int N, int K)
{
    const int BM = 128, BN = 128, BK = 8;
    __shared__ float As[BK][BM];
    __shared__ float Bs[BK][BN];

    int tid = threadIdx.x;
    int tx = tid & 15;
    int ty = tid >> 4;
    int m0 = blockIdx.y * BM;
    int n0 = blockIdx.x * BN;

    int arow = tid >> 1;
    int ac4  = (tid & 1) * 4;
    int brow = tid >> 5;
    int bc4  = (tid & 31) * 4;

    const float* Aptr = A + (size_t)(m0 + arow) * K + ac4;
    const float* Bptr = Bm + (size_t)brow * N + n0 + bc4;

    float acc[8][8];
    #pragma unroll
    for (int i = 0; i < 8; i++)
        #pragma unroll
        for (int j = 0; j < 8; j++) acc[i][j] = 0.f;

    for (int k0 = 0; k0 < K; k0 += BK) {
        float4 av = *(const float4*)(Aptr + k0);
        As[ac4 + 0][arow] = av.x;
        As[ac4 + 1][arow] = av.y;
        As[ac4 + 2][arow] = av.z;
        As[ac4 + 3][arow] = av.w;
        *(float4*)&Bs[brow][bc4] = *(const float4*)(Bptr + (size_t)k0 * N);
        __syncthreads();

        #pragma unroll
        for (int kk = 0; kk < BK; kk++) {
            float a[8], b[8];
            *(float4*)(a)     = *(float4*)&As[kk][ty * 8];
            *(float4*)(a + 4) = *(float4*)&As[kk][ty * 8 + 4];
            *(float4*)(b)     = *(float4*)&Bs[kk][tx * 8];
            *(float4*)(b + 4) = *(float4*)&Bs[kk][tx * 8 + 4];
            #pragma unroll
            for (int i = 0; i < 8; i++)
                #pragma unroll
                for (int j = 0; j < 8; j++)
                    acc[i][j] = fmaf(a[i], b[j], acc[i][j]);
        }
        __syncthreads();
    }

    float bb[8];
    *(float4*)(bb)     = *(const float4*)&bias[n0 + tx * 8];
    *(float4*)(bb + 4) = *(const float4*)&bias[n0 + tx * 8 + 4];

    #pragma unroll
    for (int i = 0; i < 8; i++) {
        float* cp = C + (size_t)(m0 + ty * 8 + i) * N + n0 + tx * 8;
        float4 v0, v1;
        v0.x = acc[i][0] + bb[0]; v0.y = acc[i][1] + bb[1];
        v0.z = acc[i][2] + bb[2]; v0.w = acc[i][3] + bb[3];
        v1.x = acc[i][4] + bb[4]; v1.y = acc[i][5] + bb[5];
        v1.z = acc[i][6] + bb[6]; v1.w = acc[i][7] + bb[7];
        *(float4*)(cp)     = v0;
        *(float4*)(cp + 4) = v1;
    }
}

// ---------------------------------------------------------------------------
// TF32 tensor-core flash attention.
// Block = 128 queries x (batch, head). 8 warps; warp owns 16 query rows.
// KV streamed in tiles of 128. QK and PV via mma.sync m16n8k8 tf32.
// smem pitches chosen so fragment loads are bank-conflict-free.
// ---------------------------------------------------------------------------
#define BQ     128
#define BKV    128
#define QKP    68    // pitch for Qs/Ks/Vs  (4*(lane/4)+lane%4 = lane -> cf)
#define PSP    132   // pitch for Ps

#define QS_OFF  0
#define KS_OFF  (QS_OFF + BQ * QKP)          // 8704
#define VS_OFF  (KS_OFF + BKV * QKP)         // 17408
#define PS_OFF  (VS_OFF + BKV * QKP)         // 26112
#define SMEM_WORDS (PS_OFF + BQ * PSP)       // 43008 words = 172032 B

__device__ __forceinline__ uint32_t f2tf(float f) {
    uint32_t u;
    asm("cvt.rna.tf32.f32 %0, %1;" : "=r"(u) : "f"(f));
    return u;
}

__device__ __forceinline__ void mma_tf32(float* d,
                                         uint32_t a0, uint32_t a1, uint32_t a2, uint32_t a3,
                                         uint32_t b0, uint32_t b1)
{
    asm volatile(
        "mma.sync.aligned.m16n8k8.row.col.f32.tf32.tf32.f32 "
        "{%0,%1,%2,%3}, {%4,%5,%6,%7}, {%8,%9}, {%0,%1,%2,%3};\n"
        : "+f"(d[0]), "+f"(d[1]), "+f"(d[2]), "+f"(d[3])
        : "r"(a0), "r"(a1), "r"(a2), "r"(a3), "r"(b0), "r"(b1));
}

__global__ __launch_bounds__(256)
void flash_attn_tc_kernel(const float* __restrict__ qkv, float* __restrict__ y)
{
    extern __shared__ uint32_t sm[];
    uint32_t* Qs = sm + QS_OFF;
    uint32_t* Ks = sm + KS_OFF;
    uint32_t* Vs = sm + VS_OFF;
    uint32_t* Ps = sm + PS_OFF;

    int tid  = threadIdx.x;
    int w    = tid >> 5;
    int lane = tid & 31;
    int gi   = lane >> 2;     // 0..7
    int tg   = lane & 3;      // 0..3
    int q0   = blockIdx.x * BQ;
    int h    = blockIdx.y;
    int b    = blockIdx.z;
    const float SCALE = 0.125f;

    size_t base = (size_t)b * SEQT * QKV3;
    int qoff = h * HDIM;
    int koff = DIMV + h * HDIM;
    int voff = 2 * DIMV + h * HDIM;

    // Load Q tile -> tf32 smem [128][QKP]
    #pragma unroll
    for (int it = 0; it < 8; it++) {
        int idx = tid + it * 256;
        int r   = idx >> 4;
        int c4  = (idx & 15) * 4;
        float4 v = *(const float4*)&qkv[base + (size_t)(q0 + r) * QKV3 + qoff + c4];
        uint4 t;
        t.x = f2tf(v.x); t.y = f2tf(v.y); t.z = f2tf(v.z); t.w = f2tf(v.w);
        *(uint4*)&Qs[r * QKP + c4] = t;
    }

    int r0 = w * 16 + gi;
    int r1 = r0 + 8;

    float m0 = -1e30f, m1 = -1e30f;
    float l0 = 0.f, l1 = 0.f;
    float o[8][4];
    #pragma unroll
    for (int j = 0; j < 8; j++)
        #pragma unroll
        for (int e = 0; e < 4; e++) o[j][e] = 0.f;

    for (int kv0 = 0; kv0 < SEQT; kv0 += BKV) {
        __syncthreads();   // previous PV readers of Vs/Ps done

        // Load K, V tiles -> tf32 smem
        #pragma unroll
        for (int it = 0; it < 8; it++) {
            int idx = tid + it * 256;
            int r   = idx >> 4;
            int c4  = (idx & 15) * 4;
            size_t row = base + (size_t)(kv0 + r) * QKV3;
            float4 kvv = *(const float4*)&qkv[row + koff + c4];
            uint4 tk;
            tk.x = f2tf(kvv.x); tk.y = f2tf(kvv.y); tk.z = f2tf(kvv.z); tk.w = f2tf(kvv.w);
            *(uint4*)&Ks[r * QKP + c4] = tk;
            float4 vv = *(const float4*)&qkv[row + voff + c4];
            uint4 tv;
            tv.x = f2tf(vv.x); tv.y = f2tf(vv.y); tv.z = f2tf(vv.z); tv.w = f2tf(vv.w);
            *(uint4*)&Vs[r * QKP + c4] = tv;
        }
        __syncthreads();

        // ---- QK: s = Q[16 x 64] @ K^T[64 x 128] ----
        float s[16][4];
        #pragma unroll
        for (int j = 0; j < 16; j++)
            #pragma unroll
            for (int e = 0; e < 4; e++) s[j][e] = 0.f;

        #pragma unroll
        for (int kk = 0; kk < 8; kk++) {
            int d0 = kk * 8;
            uint32_t a0 = Qs[r0 * QKP + d0 + tg];
            uint32_t a1 = Qs[r1 * QKP + d0 + tg];
            uint32_t a2 = Qs[r0 * QKP + d0 + tg + 4];
            uint32_t a3 = Qs[r1 * QKP + d0 + tg + 4];
            #pragma unroll
            for (int j = 0; j < 16; j++) {
                uint32_t b0 = Ks[(j * 8 + gi) * QKP + d0 + tg];
                uint32_t b1 = Ks[(j * 8 + gi) * QKP + d0 + tg + 4];
                mma_tf32(s[j], a0, a1, a2, a3, b0, b1);
            }
        }

        // ---- online softmax on fragments ----
        float mx0 = -1e30f, mx1 = -1e30f;
        #pragma unroll
        for (int j = 0; j < 16; j++) {
            mx0 = fmaxf(mx0, fmaxf(s[j][0], s[j][1]));
            mx1 = fmaxf(mx1, fmaxf(s[j][2], s[j][3]));
        }
        #pragma unroll
        for (int msk = 1; msk < 4; msk <<= 1) {
            mx0 = fmaxf(mx0, __shfl_xor_sync(0xffffffffu, mx0, msk));
            mx1 = fmaxf(mx1, __shfl_xor_sync(0xffffffffu, mx1, msk));
        }
        float mn0 = fmaxf(m0, mx0 * SCALE);
        float mn1 = fmaxf(m1, mx1 * SCALE);
        float c0 = __expf(m0 - mn0);
        float c1 = __expf(m1 - mn1);

        float sum0 = 0.f, sum1 = 0.f;
        #pragma unroll
        for (int j = 0; j < 16; j++) {
            float p0 = __expf(s[j][0] * SCALE - mn0);
            float p1 = __expf(s[j][1] * SCALE - mn0);
            float p2 = __expf(s[j][2] * SCALE - mn1);
            float p3 = __expf(s[j][3] * SCALE - mn1);
            sum0 += p0 + p1;
            sum1 += p2 + p3;
            uint2 u01 = make_uint2(f2tf(p0), f2tf(p1));
            uint2 u23 = make_uint2(f2tf(p2), f2tf(p3));
            *(uint2*)&Ps[r0 * PSP + j * 8 + 2 * tg] = u01;
            *(uint2*)&Ps[r1 * PSP + j * 8 + 2 * tg] = u23;
        }
        #pragma unroll
        for (int msk = 1; msk < 4; msk <<= 1) {
            sum0 += __shfl_xor_sync(0xffffffffu, sum0, msk);
            sum1 += __shfl_xor_sync(0xffffffffu, sum1, msk);
        }
        l0 = l0 * c0 + sum0;
        l1 = l1 * c1 + sum1;
        m0 = mn0;
        m1 = mn1;
        #pragma unroll
        for (int j = 0; j < 8; j++) {
            o[j][0] *= c0; o[j][1] *= c0;
            o[j][2] *= c1; o[j][3] *= c1;
        }
        __syncthreads();   // Ps visible to all lanes of this warp's rows

        // ---- PV: o += P[16 x 128] @ V[128 x 64] ----
        #pragma unroll
        for (int kk = 0; kk < 16; kk++) {
            int k0 = kk * 8;
            uint32_t a0 = Ps[r0 * PSP + k0 + tg];
            uint32_t a1 = Ps[r1 * PSP + k0 + tg];
            uint32_t a2 = Ps[r0 * PSP + k0 + tg + 4];
            uint32_t a3 = Ps[r1 * PSP + k0 + tg + 4];
            #pragma unroll
            for (int j = 0; j < 8; j++) {
                uint32_t b0 = Vs[(k0 + tg) * QKP + j * 8 + gi];
                uint32_t b1 = Vs[(k0 + tg + 4) * QKP + j * 8 + gi];
                mma_tf32(o[j], a0, a1, a2, a3, b0, b1);
            }
        }
    }

    // Epilogue
    float inv0 = 1.f / l0;
    float inv1 = 1.f / l1;
    size_t row0 = (size_t)(b * SEQT + q0 + r0) * DIMV + h * HDIM;
    size_t row1 = (size_t)(b * SEQT + q0 + r1) * DIMV + h * HDIM;
    #pragma unroll
    for (int j = 0; j < 8; j++) {
        int col = j * 8 + 2 * tg;
        *(float2*)&y[row0 + col] = make_float2(o[j][0] * inv0, o[j][1] * inv0);
        *(float2*)&y[row1 + col] = make_float2(o[j][2] * inv1, o[j][3] * inv1);
    }
}

// ---------------------------------------------------------------------------
extern "C" void kernel_launch(void* const* d_in, const int* in_sizes, int n_in,
                              void* d_out, int out_size)
{
    const float* x      = (const float*)d_in[0];
    const float* W_qkv  = (const float*)d_in[1];
    const float* b_qkv  = (const float*)d_in[2];
    const float* W_proj = (const float*)d_in[3];
    const float* b_proj = (const float*)d_in[4];
    float* out = (float*)d_out;

    float* qkv;
    float* yb;
    cudaGetSymbolAddress((void**)&qkv, g_qkv);
    cudaGetSymbolAddress((void**)&yb, g_y);

    // 1) QKV projection
    {
        dim3 grid(QKV3 / 128, MROWS / 128);
        sgemm_bias_kernel<<<grid, 256>>>(x, W_qkv, b_qkv, qkv, MROWS, QKV3, DIMV);
    }

    // 2) Tensor-core flash attention
    {
        int smem_bytes = SMEM_WORDS * 4;
        cudaFuncSetAttribute(flash_attn_tc_kernel,
                             cudaFuncAttributeMaxDynamicSharedMemorySize, smem_bytes);
        dim3 grid(SEQT / BQ, NHEAD, BATCH);
        flash_attn_tc_kernel<<<grid, 256, smem_bytes>>>(qkv, yb);
    }

    // 3) Output projection
    {
        dim3 grid(DIMV / 128, MROWS / 128);
        sgemm_bias_kernel<<<grid, 256>>>(yb, W_proj, b_proj, out, MROWS, DIMV, DIMV);
    }
}

// round 5
// speedup vs baseline: 8.2013x; 1.3713x over previous
#include <cuda_runtime.h>
#include <cstdint>

#define DIMV   768
#define QKV3   2304
#define BATCH  8
#define SEQT   1024
#define NHEAD  12
#define HDIM   64
#define MROWS  (BATCH * SEQT)   // 8192

__device__ float g_qkv[(size_t)MROWS * QKV3];   // ~75.5 MB
__device__ float g_y[(size_t)MROWS * DIMV];     // ~25 MB

// ---------------------------------------------------------------------------
// Shared helpers: tf32 conversion + m16n8k8 tf32 mma
// ---------------------------------------------------------------------------
__device__ __forceinline__ uint32_t f2tf(float f) {
    uint32_t u;
    asm("cvt.rna.tf32.f32 %0, %1;" : "=r"(u) : "f"(f));
    return u;
}

__device__ __forceinline__ void cvt_hl(float f, uint32_t& h, uint32_t& l) {
    h = f2tf(f);
    l = f2tf(f - __uint_as_float(h));
}

__device__ __forceinline__ void mma_tf32(float* d,
                                         uint32_t a0, uint32_t a1, uint32_t a2, uint32_t a3,
                                         uint32_t b0, uint32_t b1)
{
    asm volatile(
        "mma.sync.aligned.m16n8k8.row.col.f32.tf32.tf32.f32 "
        "{%0,%1,%2,%3}, {%4,%5,%6,%7}, {%8,%9}, {%0,%1,%2,%3};\n"
        : "+f"(d[0]), "+f"(d[1]), "+f"(d[2]), "+f"(d[3])
        : "r"(a0), "r"(a1), "r"(a2), "r"(a3), "r"(b0), "r"(b1));
}

// ---------------------------------------------------------------------------
// 3xTF32 tensor-core GEMM: C[M,N] = A[M,K] @ B[K,N] + bias[N]
// CTA tile 128x128, BK=16, 8 warps (4 along M x 2 along N), warp tile 32x64.
// A smem [row][k] pitch 20 (frag reads conflict-free),
// B smem [k][n]  pitch 136 (natural stores sequential, frag reads cf).
// acc += Ahi*Bhi + Alo*Bhi + Ahi*Blo  (fp32-grade accuracy).
// ---------------------------------------------------------------------------
#define GBK  16
#define AP   20
#define BP   136

__global__ __launch_bounds__(256, 2)
void tf32_gemm_bias_kernel(const float* __restrict__ A,
                           const float* __restrict__ Bm,
                           const float* __restrict__ bias,
                           float* __restrict__ C,
                           int M, int N, int K)
{
    __shared__ uint32_t Ah[128 * AP];
    __shared__ uint32_t Al[128 * AP];
    __shared__ uint32_t Bh[GBK * BP];
    __shared__ uint32_t Bl[GBK * BP];

    int tid  = threadIdx.x;
    int w    = tid >> 5;
    int lane = tid & 31;
    int gi   = lane >> 2;
    int tg   = lane & 3;
    int wm   = (w & 3) * 32;      // warp row offset
    int wn   = (w >> 2) * 64;     // warp col offset
    int m0   = blockIdx.y * 128;
    int n0   = blockIdx.x * 128;

    // A loads: 512 float4 per tile; thread handles i=tid and i=tid+256
    int ar0 = tid >> 2;             // 0..63
    int akc = (tid & 3) * 4;
    // B loads: 512 float4; krow = i>>5, nc = (i&31)*4
    int bk0 = tid >> 5;             // 0..7
    int bnc = (tid & 31) * 4;

    const float* Ap0 = A + (size_t)(m0 + ar0) * K + akc;
    const float* Ap1 = A + (size_t)(m0 + ar0 + 64) * K + akc;
    const float* Bp0 = Bm + (size_t)bk0 * N + n0 + bnc;
    const float* Bp1 = Bm + (size_t)(bk0 + 8) * N + n0 + bnc;

    float acc[2][8][4];
    #pragma unroll
    for (int mi = 0; mi < 2; mi++)
        #pragma unroll
        for (int nb = 0; nb < 8; nb++)
            #pragma unroll
            for (int e = 0; e < 4; e++) acc[mi][nb][e] = 0.f;

    float4 pa0 = *(const float4*)Ap0;
    float4 pa1 = *(const float4*)Ap1;
    float4 pb0 = *(const float4*)Bp0;
    float4 pb1 = *(const float4*)Bp1;

    for (int k0 = 0; k0 < K; k0 += GBK) {
        // Store current tile (convert to hi/lo tf32)
        {
            uint4 h, l;
            cvt_hl(pa0.x, h.x, l.x); cvt_hl(pa0.y, h.y, l.y);
            cvt_hl(pa0.z, h.z, l.z); cvt_hl(pa0.w, h.w, l.w);
            *(uint4*)&Ah[ar0 * AP + akc] = h;
            *(uint4*)&Al[ar0 * AP + akc] = l;
            cvt_hl(pa1.x, h.x, l.x); cvt_hl(pa1.y, h.y, l.y);
            cvt_hl(pa1.z, h.z, l.z); cvt_hl(pa1.w, h.w, l.w);
            *(uint4*)&Ah[(ar0 + 64) * AP + akc] = h;
            *(uint4*)&Al[(ar0 + 64) * AP + akc] = l;
            cvt_hl(pb0.x, h.x, l.x); cvt_hl(pb0.y, h.y, l.y);
            cvt_hl(pb0.z, h.z, l.z); cvt_hl(pb0.w, h.w, l.w);
            *(uint4*)&Bh[bk0 * BP + bnc] = h;
            *(uint4*)&Bl[bk0 * BP + bnc] = l;
            cvt_hl(pb1.x, h.x, l.x); cvt_hl(pb1.y, h.y, l.y);
            cvt_hl(pb1.z, h.z, l.z); cvt_hl(pb1.w, h.w, l.w);
            *(uint4*)&Bh[(bk0 + 8) * BP + bnc] = h;
            *(uint4*)&Bl[(bk0 + 8) * BP + bnc] = l;
        }
        __syncthreads();

        // Prefetch next tile
        if (k0 + GBK < K) {
            Ap0 += GBK; Ap1 += GBK;
            Bp0 += (size_t)GBK * N; Bp1 += (size_t)GBK * N;
            pa0 = *(const float4*)Ap0;
            pa1 = *(const float4*)Ap1;
            pb0 = *(const float4*)Bp0;
            pb1 = *(const float4*)Bp1;
        }

        // MMA over 2 k-steps of 8
        #pragma unroll
        for (int ks = 0; ks < 2; ks++) {
            int kk = ks * 8;
            uint32_t ah[2][4], al[2][4];
            #pragma unroll
            for (int mi = 0; mi < 2; mi++) {
                int r = wm + mi * 16 + gi;
                ah[mi][0] = Ah[r * AP + kk + tg];
                ah[mi][1] = Ah[(r + 8) * AP + kk + tg];
                ah[mi][2] = Ah[r * AP + kk + tg + 4];
                ah[mi][3] = Ah[(r + 8) * AP + kk + tg + 4];
                al[mi][0] = Al[r * AP + kk + tg];
                al[mi][1] = Al[(r + 8) * AP + kk + tg];
                al[mi][2] = Al[r * AP + kk + tg + 4];
                al[mi][3] = Al[(r + 8) * AP + kk + tg + 4];
            }
            #pragma unroll
            for (int nb = 0; nb < 8; nb++) {
                int c = wn + nb * 8 + gi;
                uint32_t bh0 = Bh[(kk + tg) * BP + c];
                uint32_t bh1 = Bh[(kk + tg + 4) * BP + c];
                uint32_t bl0 = Bl[(kk + tg) * BP + c];
                uint32_t bl1 = Bl[(kk + tg + 4) * BP + c];
                #pragma unroll
                for (int mi = 0; mi < 2; mi++) {
                    mma_tf32(acc[mi][nb], ah[mi][0], ah[mi][1], ah[mi][2], ah[mi][3], bh0, bh1);
                    mma_tf32(acc[mi][nb], al[mi][0], al[mi][1], al[mi][2], al[mi][3], bh0, bh1);
                    mma_tf32(acc[mi][nb], ah[mi][0], ah[mi][1], ah[mi][2], ah[mi][3], bl0, bl1);
                }
            }
        }
        __syncthreads();
    }

    // Epilogue: bias + store (float2 per fragment row)
    #pragma unroll
    for (int mi = 0; mi < 2; mi++) {
        int r = m0 + wm + mi * 16 + gi;
        #pragma unroll
        for (int nb = 0; nb < 8; nb++) {
            int c = n0 + wn + nb * 8 + 2 * tg;
            float2 bv = *(const float2*)&bias[c];
            *(float2*)&C[(size_t)r * N + c] =
                make_float2(acc[mi][nb][0] + bv.x, acc[mi][nb][1] + bv.y);
            *(float2*)&C[(size_t)(r + 8) * N + c] =
                make_float2(acc[mi][nb][2] + bv.x, acc[mi][nb][3] + bv.y);
        }
    }
}

// ---------------------------------------------------------------------------
// TF32 tensor-core flash attention (unchanged from R3).
// ---------------------------------------------------------------------------
#define BQ     128
#define BKV    128
#define QKP    68
#define PSP    132

#define QS_OFF  0
#define KS_OFF  (QS_OFF + BQ * QKP)
#define VS_OFF  (KS_OFF + BKV * QKP)
#define PS_OFF  (VS_OFF + BKV * QKP)
#define SMEM_WORDS (PS_OFF + BQ * PSP)

__global__ __launch_bounds__(256)
void flash_attn_tc_kernel(const float* __restrict__ qkv, float* __restrict__ y)
{
    extern __shared__ uint32_t sm[];
    uint32_t* Qs = sm + QS_OFF;
    uint32_t* Ks = sm + KS_OFF;
    uint32_t* Vs = sm + VS_OFF;
    uint32_t* Ps = sm + PS_OFF;

    int tid  = threadIdx.x;
    int w    = tid >> 5;
    int lane = tid & 31;
    int gi   = lane >> 2;
    int tg   = lane & 3;
    int q0   = blockIdx.x * BQ;
    int h    = blockIdx.y;
    int b    = blockIdx.z;
    const float SCALE = 0.125f;

    size_t base = (size_t)b * SEQT * QKV3;
    int qoff = h * HDIM;
    int koff = DIMV + h * HDIM;
    int voff = 2 * DIMV + h * HDIM;

    #pragma unroll
    for (int it = 0; it < 8; it++) {
        int idx = tid + it * 256;
        int r   = idx >> 4;
        int c4  = (idx & 15) * 4;
        float4 v = *(const float4*)&qkv[base + (size_t)(q0 + r) * QKV3 + qoff + c4];
        uint4 t;
        t.x = f2tf(v.x); t.y = f2tf(v.y); t.z = f2tf(v.z); t.w = f2tf(v.w);
        *(uint4*)&Qs[r * QKP + c4] = t;
    }

    int r0 = w * 16 + gi;
    int r1 = r0 + 8;

    float m0 = -1e30f, m1 = -1e30f;
    float l0 = 0.f, l1 = 0.f;
    float o[8][4];
    #pragma unroll
    for (int j = 0; j < 8; j++)
        #pragma unroll
        for (int e = 0; e < 4; e++) o[j][e] = 0.f;

    for (int kv0 = 0; kv0 < SEQT; kv0 += BKV) {
        __syncthreads();

        #pragma unroll
        for (int it = 0; it < 8; it++) {
            int idx = tid + it * 256;
            int r   = idx >> 4;
            int c4  = (idx & 15) * 4;
            size_t row = base + (size_t)(kv0 + r) * QKV3;
            float4 kvv = *(const float4*)&qkv[row + koff + c4];
            uint4 tk;
            tk.x = f2tf(kvv.x); tk.y = f2tf(kvv.y); tk.z = f2tf(kvv.z); tk.w = f2tf(kvv.w);
            *(uint4*)&Ks[r * QKP + c4] = tk;
            float4 vv = *(const float4*)&qkv[row + voff + c4];
            uint4 tv;
            tv.x = f2tf(vv.x); tv.y = f2tf(vv.y); tv.z = f2tf(vv.z); tv.w = f2tf(vv.w);
            *(uint4*)&Vs[r * QKP + c4] = tv;
        }
        __syncthreads();

        float s[16][4];
        #pragma unroll
        for (int j = 0; j < 16; j++)
            #pragma unroll
            for (int e = 0; e < 4; e++) s[j][e] = 0.f;

        #pragma unroll
        for (int kk = 0; kk < 8; kk++) {
            int d0 = kk * 8;
            uint32_t a0 = Qs[r0 * QKP + d0 + tg];
            uint32_t a1 = Qs[r1 * QKP + d0 + tg];
            uint32_t a2 = Qs[r0 * QKP + d0 + tg + 4];
            uint32_t a3 = Qs[r1 * QKP + d0 + tg + 4];
            #pragma unroll
            for (int j = 0; j < 16; j++) {
                uint32_t b0 = Ks[(j * 8 + gi) * QKP + d0 + tg];
                uint32_t b1 = Ks[(j * 8 + gi) * QKP + d0 + tg + 4];
                mma_tf32(s[j], a0, a1, a2, a3, b0, b1);
            }
        }

        float mx0 = -1e30f, mx1 = -1e30f;
        #pragma unroll
        for (int j = 0; j < 16; j++) {
            mx0 = fmaxf(mx0, fmaxf(s[j][0], s[j][1]));
            mx1 = fmaxf(mx1, fmaxf(s[j][2], s[j][3]));
        }
        #pragma unroll
        for (int msk = 1; msk < 4; msk <<= 1) {
            mx0 = fmaxf(mx0, __shfl_xor_sync(0xffffffffu, mx0, msk));
            mx1 = fmaxf(mx1, __shfl_xor_sync(0xffffffffu, mx1, msk));
        }
        float mn0 = fmaxf(m0, mx0 * SCALE);
        float mn1 = fmaxf(m1, mx1 * SCALE);
        float c0 = __expf(m0 - mn0);
        float c1 = __expf(m1 - mn1);

        float sum0 = 0.f, sum1 = 0.f;
        #pragma unroll
        for (int j = 0; j < 16; j++) {
            float p0 = __expf(s[j][0] * SCALE - mn0);
            float p1 = __expf(s[j][1] * SCALE - mn0);
            float p2 = __expf(s[j][2] * SCALE - mn1);
            float p3 = __expf(s[j][3] * SCALE - mn1);
            sum0 += p0 + p1;
            sum1 += p2 + p3;
            uint2 u01 = make_uint2(f2tf(p0), f2tf(p1));
            uint2 u23 = make_uint2(f2tf(p2), f2tf(p3));
            *(uint2*)&Ps[r0 * PSP + j * 8 + 2 * tg] = u01;
            *(uint2*)&Ps[r1 * PSP + j * 8 + 2 * tg] = u23;
        }
        #pragma unroll
        for (int msk = 1; msk < 4; msk <<= 1) {
            sum0 += __shfl_xor_sync(0xffffffffu, sum0, msk);
            sum1 += __shfl_xor_sync(0xffffffffu, sum1, msk);
        }
        l0 = l0 * c0 + sum0;
        l1 = l1 * c1 + sum1;
        m0 = mn0;
        m1 = mn1;
        #pragma unroll
        for (int j = 0; j < 8; j++) {
            o[j][0] *= c0; o[j][1] *= c0;
            o[j][2] *= c1; o[j][3] *= c1;
        }
        __syncthreads();

        #pragma unroll
        for (int kk = 0; kk < 16; kk++) {
            int k0 = kk * 8;
            uint32_t a0 = Ps[r0 * PSP + k0 + tg];
            uint32_t a1 = Ps[r1 * PSP + k0 + tg];
            uint32_t a2 = Ps[r0 * PSP + k0 + tg + 4];
            uint32_t a3 = Ps[r1 * PSP + k0 + tg + 4];
            #pragma unroll
            for (int j = 0; j < 8; j++) {
                uint32_t b0 = Vs[(k0 + tg) * QKP + j * 8 + gi];
                uint32_t b1 = Vs[(k0 + tg + 4) * QKP + j * 8 + gi];
                mma_tf32(o[j], a0, a1, a2, a3, b0, b1);
            }
        }
    }

    float inv0 = 1.f / l0;
    float inv1 = 1.f / l1;
    size_t row0 = (size_t)(b * SEQT + q0 + r0) * DIMV + h * HDIM;
    size_t row1 = (size_t)(b * SEQT + q0 + r1) * DIMV + h * HDIM;
    #pragma unroll
    for (int j = 0; j < 8; j++) {
        int col = j * 8 + 2 * tg;
        *(float2*)&y[row0 + col] = make_float2(o[j][0] * inv0, o[j][1] * inv0);
        *(float2*)&y[row1 + col] = make_float2(o[j][2] * inv1, o[j][3] * inv1);
    }
}

// ---------------------------------------------------------------------------
extern "C" void kernel_launch(void* const* d_in, const int* in_sizes, int n_in,
                              void* d_out, int out_size)
{
    const float* x      = (const float*)d_in[0];
    const float* W_qkv  = (const float*)d_in[1];
    const float* b_qkv  = (const float*)d_in[2];
    const float* W_proj = (const float*)d_in[3];
    const float* b_proj = (const float*)d_in[4];
    float* out = (float*)d_out;

    float* qkv;
    float* yb;
    cudaGetSymbolAddress((void**)&qkv, g_qkv);
    cudaGetSymbolAddress((void**)&yb, g_y);

    // 1) QKV projection (3xTF32 tensor cores)
    {
        dim3 grid(QKV3 / 128, MROWS / 128);
        tf32_gemm_bias_kernel<<<grid, 256>>>(x, W_qkv, b_qkv, qkv, MROWS, QKV3, DIMV);
    }

    // 2) Tensor-core flash attention
    {
        int smem_bytes = SMEM_WORDS * 4;
        cudaFuncSetAttribute(flash_attn_tc_kernel,
                             cudaFuncAttributeMaxDynamicSharedMemorySize, smem_bytes);
        dim3 grid(SEQT / BQ, NHEAD, BATCH);
        flash_attn_tc_kernel<<<grid, 256, smem_bytes>>>(qkv, yb);
    }

    // 3) Output projection (3xTF32 tensor cores)
    {
        dim3 grid(DIMV / 128, MROWS / 128);
        tf32_gemm_bias_kernel<<<grid, 256>>>(yb, W_proj, b_proj, out, MROWS, DIMV, DIMV);
    }
}

// round 6
// speedup vs baseline: 11.1226x; 1.3562x over previous
#include <cuda_runtime.h>
#include <cuda_bf16.h>
#include <cstdint>

#define DIMV   768
#define QKV3   2304
#define BATCH  8
#define SEQT   1024
#define NHEAD  12
#define HDIM   64
#define MROWS  (BATCH * SEQT)   // 8192

__device__ float g_qkv[(size_t)MROWS * QKV3];   // ~75.5 MB
__device__ float g_y[(size_t)MROWS * DIMV];     // ~25 MB

// ---------------------------------------------------------------------------
// Helpers
// ---------------------------------------------------------------------------
__device__ __forceinline__ uint32_t f2tf(float f) {
    uint32_t u;
    asm("cvt.rna.tf32.f32 %0, %1;" : "=r"(u) : "f"(f));
    return u;
}

__device__ __forceinline__ void mma_tf32(float* d,
                                         uint32_t a0, uint32_t a1, uint32_t a2, uint32_t a3,
                                         uint32_t b0, uint32_t b1)
{
    asm volatile(
        "mma.sync.aligned.m16n8k8.row.col.f32.tf32.tf32.f32 "
        "{%0,%1,%2,%3}, {%4,%5,%6,%7}, {%8,%9}, {%0,%1,%2,%3};\n"
        : "+f"(d[0]), "+f"(d[1]), "+f"(d[2]), "+f"(d[3])
        : "r"(a0), "r"(a1), "r"(a2), "r"(a3), "r"(b0), "r"(b1));
}

__device__ __forceinline__ void mma_bf16(float* d,
                                         uint32_t a0, uint32_t a1, uint32_t a2, uint32_t a3,
                                         uint32_t b0, uint32_t b1)
{
    asm volatile(
        "mma.sync.aligned.m16n8k16.row.col.f32.bf16.bf16.f32 "
        "{%0,%1,%2,%3}, {%4,%5,%6,%7}, {%8,%9}, {%0,%1,%2,%3};\n"
        : "+f"(d[0]), "+f"(d[1]), "+f"(d[2]), "+f"(d[3])
        : "r"(a0), "r"(a1), "r"(a2), "r"(a3), "r"(b0), "r"(b1));
}

// Split two floats (consecutive k: a = lower k index) into packed bf16 hi/lo.
__device__ __forceinline__ void split2(float a, float b, uint32_t& h, uint32_t& l)
{
    __nv_bfloat16 ah = __float2bfloat16(a);
    __nv_bfloat16 bh = __float2bfloat16(b);
    h = ((uint32_t)__bfloat16_as_ushort(bh) << 16) | (uint32_t)__bfloat16_as_ushort(ah);
    __nv_bfloat16 al = __float2bfloat16(a - __bfloat162float(ah));
    __nv_bfloat16 bl = __float2bfloat16(b - __bfloat162float(bh));
    l = ((uint32_t)__bfloat16_as_ushort(bl) << 16) | (uint32_t)__bfloat16_as_ushort(al);
}

// ---------------------------------------------------------------------------
// bf16x3 tensor-core GEMM: C[M,N] = A[M,K] @ B[K,N] + bias[N]
// CTA 128x128, BK=16, 8 warps (4M x 2N), warp tile 32x64, mma m16n8k16.
// acc += Ah*Bh + Al*Bh + Ah*Bl  (~16-bit mantissa accuracy, fp32 accumulate).
// A smem: [row][k-pair] pitch 12 (frag reads conflict-free).
// B smem: [k-pair][n]   pitch 136 (stores sequential, frag reads cf).
// ---------------------------------------------------------------------------
#define GBK  16
#define AP   12
#define BP   136

__global__ __launch_bounds__(256, 2)
void bf16x3_gemm_bias_kernel(const float* __restrict__ A,
                             const float* __restrict__ Bm,
                             const float* __restrict__ bias,
                             float* __restrict__ C,
                             int M, int N, int K)
{
    __shared__ uint32_t Ah[128 * AP];
    __shared__ uint32_t Al[128 * AP];
    __shared__ uint32_t Bh[8 * BP];
    __shared__ uint32_t Bl[8 * BP];

    int tid  = threadIdx.x;
    int w    = tid >> 5;
    int lane = tid & 31;
    int gi   = lane >> 2;
    int tg   = lane & 3;
    int wm   = (w & 3) * 32;
    int wn   = (w >> 2) * 64;
    int m0   = blockIdx.y * 128;
    int n0   = blockIdx.x * 128;

    // A loads: rows ar0, ar0+64; 4 floats at k-offset akc
    int ar0 = tid >> 2;             // 0..63
    int akc = (tid & 3) * 4;        // 0,4,8,12
    int apk = (tid & 3) * 2;        // pair index 0,2,4,6
    // B loads: k-rows 2*bp, 2*bp+1 at cols bnc..bnc+3
    int bp  = tid >> 5;             // 0..7
    int bnc = (tid & 31) * 4;

    const float* Ap0 = A + (size_t)(m0 + ar0) * K + akc;
    const float* Ap1 = A + (size_t)(m0 + ar0 + 64) * K + akc;
    const float* Bp0 = Bm + (size_t)(2 * bp) * N + n0 + bnc;
    const float* Bp1 = Bm + (size_t)(2 * bp + 1) * N + n0 + bnc;

    float acc[2][8][4];
    #pragma unroll
    for (int mi = 0; mi < 2; mi++)
        #pragma unroll
        for (int nb = 0; nb < 8; nb++)
            #pragma unroll
            for (int e = 0; e < 4; e++) acc[mi][nb][e] = 0.f;

    float4 pa0 = *(const float4*)Ap0;
    float4 pa1 = *(const float4*)Ap1;
    float4 pb0 = *(const float4*)Bp0;
    float4 pb1 = *(const float4*)Bp1;

    for (int k0 = 0; k0 < K; k0 += GBK) {
        // Convert + store current tile
        {
            uint2 h2, l2;
            split2(pa0.x, pa0.y, h2.x, l2.x);
            split2(pa0.z, pa0.w, h2.y, l2.y);
            *(uint2*)&Ah[ar0 * AP + apk] = h2;
            *(uint2*)&Al[ar0 * AP + apk] = l2;
            split2(pa1.x, pa1.y, h2.x, l2.x);
            split2(pa1.z, pa1.w, h2.y, l2.y);
            *(uint2*)&Ah[(ar0 + 64) * AP + apk] = h2;
            *(uint2*)&Al[(ar0 + 64) * AP + apk] = l2;

            uint4 h4, l4;   // pair j: (k=2bp col j, k=2bp+1 col j)
            split2(pb0.x, pb1.x, h4.x, l4.x);
            split2(pb0.y, pb1.y, h4.y, l4.y);
            split2(pb0.z, pb1.z, h4.z, l4.z);
            split2(pb0.w, pb1.w, h4.w, l4.w);
            *(uint4*)&Bh[bp * BP + bnc] = h4;
            *(uint4*)&Bl[bp * BP + bnc] = l4;
        }
        __syncthreads();

        // Prefetch next tile
        if (k0 + GBK < K) {
            Ap0 += GBK; Ap1 += GBK;
            Bp0 += (size_t)GBK * N; Bp1 += (size_t)GBK * N;
            pa0 = *(const float4*)Ap0;
            pa1 = *(const float4*)Ap1;
            pb0 = *(const float4*)Bp0;
            pb1 = *(const float4*)Bp1;
        }

        // Single k16 step: 2m x 8n x 3 terms = 48 mma
        uint32_t ah[2][4], al[2][4];
        #pragma unroll
        for (int mi = 0; mi < 2; mi++) {
            int r = wm + mi * 16 + gi;
            ah[mi][0] = Ah[r * AP + tg];
            ah[mi][1] = Ah[(r + 8) * AP + tg];
            ah[mi][2] = Ah[r * AP + tg + 4];
            ah[mi][3] = Ah[(r + 8) * AP + tg + 4];
            al[mi][0] = Al[r * AP + tg];
            al[mi][1] = Al[(r + 8) * AP + tg];
            al[mi][2] = Al[r * AP + tg + 4];
            al[mi][3] = Al[(r + 8) * AP + tg + 4];
        }
        #pragma unroll
        for (int nb = 0; nb < 8; nb++) {
            int c = wn + nb * 8 + gi;
            uint32_t bh0 = Bh[tg * BP + c];
            uint32_t bh1 = Bh[(tg + 4) * BP + c];
            uint32_t bl0 = Bl[tg * BP + c];
            uint32_t bl1 = Bl[(tg + 4) * BP + c];
            #pragma unroll
            for (int mi = 0; mi < 2; mi++) {
                mma_bf16(acc[mi][nb], ah[mi][0], ah[mi][1], ah[mi][2], ah[mi][3], bh0, bh1);
                mma_bf16(acc[mi][nb], al[mi][0], al[mi][1], al[mi][2], al[mi][3], bh0, bh1);
                mma_bf16(acc[mi][nb], ah[mi][0], ah[mi][1], ah[mi][2], ah[mi][3], bl0, bl1);
            }
        }
        __syncthreads();
    }

    // Epilogue: bias + store
    #pragma unroll
    for (int mi = 0; mi < 2; mi++) {
        int r = m0 + wm + mi * 16 + gi;
        #pragma unroll
        for (int nb = 0; nb < 8; nb++) {
            int c = n0 + wn + nb * 8 + 2 * tg;
            float2 bv = *(const float2*)&bias[c];
            *(float2*)&C[(size_t)r * N + c] =
                make_float2(acc[mi][nb][0] + bv.x, acc[mi][nb][1] + bv.y);
            *(float2*)&C[(size_t)(r + 8) * N + c] =
                make_float2(acc[mi][nb][2] + bv.x, acc[mi][nb][3] + bv.y);
        }
    }
}

// ---------------------------------------------------------------------------
// TF32 tensor-core flash attention (unchanged).
// ---------------------------------------------------------------------------
#define BQ     128
#define BKV    128
#define QKP    68
#define PSP    132

#define QS_OFF  0
#define KS_OFF  (QS_OFF + BQ * QKP)
#define VS_OFF  (KS_OFF + BKV * QKP)
#define PS_OFF  (VS_OFF + BKV * QKP)
#define SMEM_WORDS (PS_OFF + BQ * PSP)

__global__ __launch_bounds__(256)
void flash_attn_tc_kernel(const float* __restrict__ qkv, float* __restrict__ y)
{
    extern __shared__ uint32_t sm[];
    uint32_t* Qs = sm + QS_OFF;
    uint32_t* Ks = sm + KS_OFF;
    uint32_t* Vs = sm + VS_OFF;
    uint32_t* Ps = sm + PS_OFF;

    int tid  = threadIdx.x;
    int w    = tid >> 5;
    int lane = tid & 31;
    int gi   = lane >> 2;
    int tg   = lane & 3;
    int q0   = blockIdx.x * BQ;
    int h    = blockIdx.y;
    int b    = blockIdx.z;
    const float SCALE = 0.125f;

    size_t base = (size_t)b * SEQT * QKV3;
    int qoff = h * HDIM;
    int koff = DIMV + h * HDIM;
    int voff = 2 * DIMV + h * HDIM;

    #pragma unroll
    for (int it = 0; it < 8; it++) {
        int idx = tid + it * 256;
        int r   = idx >> 4;
        int c4  = (idx & 15) * 4;
        float4 v = *(const float4*)&qkv[base + (size_t)(q0 + r) * QKV3 + qoff + c4];
        uint4 t;
        t.x = f2tf(v.x); t.y = f2tf(v.y); t.z = f2tf(v.z); t.w = f2tf(v.w);
        *(uint4*)&Qs[r * QKP + c4] = t;
    }

    int r0 = w * 16 + gi;
    int r1 = r0 + 8;

    float m0 = -1e30f, m1 = -1e30f;
    float l0 = 0.f, l1 = 0.f;
    float o[8][4];
    #pragma unroll
    for (int j = 0; j < 8; j++)
        #pragma unroll
        for (int e = 0; e < 4; e++) o[j][e] = 0.f;

    for (int kv0 = 0; kv0 < SEQT; kv0 += BKV) {
        __syncthreads();

        #pragma unroll
        for (int it = 0; it < 8; it++) {
            int idx = tid + it * 256;
            int r   = idx >> 4;
            int c4  = (idx & 15) * 4;
            size_t row = base + (size_t)(kv0 + r) * QKV3;
            float4 kvv = *(const float4*)&qkv[row + koff + c4];
            uint4 tk;
            tk.x = f2tf(kvv.x); tk.y = f2tf(kvv.y); tk.z = f2tf(kvv.z); tk.w = f2tf(kvv.w);
            *(uint4*)&Ks[r * QKP + c4] = tk;
            float4 vv = *(const float4*)&qkv[row + voff + c4];
            uint4 tv;
            tv.x = f2tf(vv.x); tv.y = f2tf(vv.y); tv.z = f2tf(vv.z); tv.w = f2tf(vv.w);
            *(uint4*)&Vs[r * QKP + c4] = tv;
        }
        __syncthreads();

        float s[16][4];
        #pragma unroll
        for (int j = 0; j < 16; j++)
            #pragma unroll
            for (int e = 0; e < 4; e++) s[j][e] = 0.f;

        #pragma unroll
        for (int kk = 0; kk < 8; kk++) {
            int d0 = kk * 8;
            uint32_t a0 = Qs[r0 * QKP + d0 + tg];
            uint32_t a1 = Qs[r1 * QKP + d0 + tg];
            uint32_t a2 = Qs[r0 * QKP + d0 + tg + 4];
            uint32_t a3 = Qs[r1 * QKP + d0 + tg + 4];
            #pragma unroll
            for (int j = 0; j < 16; j++) {
                uint32_t b0 = Ks[(j * 8 + gi) * QKP + d0 + tg];
                uint32_t b1 = Ks[(j * 8 + gi) * QKP + d0 + tg + 4];
                mma_tf32(s[j], a0, a1, a2, a3, b0, b1);
            }
        }

        float mx0 = -1e30f, mx1 = -1e30f;
        #pragma unroll
        for (int j = 0; j < 16; j++) {
            mx0 = fmaxf(mx0, fmaxf(s[j][0], s[j][1]));
            mx1 = fmaxf(mx1, fmaxf(s[j][2], s[j][3]));
        }
        #pragma unroll
        for (int msk = 1; msk < 4; msk <<= 1) {
            mx0 = fmaxf(mx0, __shfl_xor_sync(0xffffffffu, mx0, msk));
            mx1 = fmaxf(mx1, __shfl_xor_sync(0xffffffffu, mx1, msk));
        }
        float mn0 = fmaxf(m0, mx0 * SCALE);
        float mn1 = fmaxf(m1, mx1 * SCALE);
        float c0 = __expf(m0 - mn0);
        float c1 = __expf(m1 - mn1);

        float sum0 = 0.f, sum1 = 0.f;
        #pragma unroll
        for (int j = 0; j < 16; j++) {
            float p0 = __expf(s[j][0] * SCALE - mn0);
            float p1 = __expf(s[j][1] * SCALE - mn0);
            float p2 = __expf(s[j][2] * SCALE - mn1);
            float p3 = __expf(s[j][3] * SCALE - mn1);
            sum0 += p0 + p1;
            sum1 += p2 + p3;
            uint2 u01 = make_uint2(f2tf(p0), f2tf(p1));
            uint2 u23 = make_uint2(f2tf(p2), f2tf(p3));
            *(uint2*)&Ps[r0 * PSP + j * 8 + 2 * tg] = u01;
            *(uint2*)&Ps[r1 * PSP + j * 8 + 2 * tg] = u23;
        }
        #pragma unroll
        for (int msk = 1; msk < 4; msk <<= 1) {
            sum0 += __shfl_xor_sync(0xffffffffu, sum0, msk);
            sum1 += __shfl_xor_sync(0xffffffffu, sum1, msk);
        }
        l0 = l0 * c0 + sum0;
        l1 = l1 * c1 + sum1;
        m0 = mn0;
        m1 = mn1;
        #pragma unroll
        for (int j = 0; j < 8; j++) {
            o[j][0] *= c0; o[j][1] *= c0;
            o[j][2] *= c1; o[j][3] *= c1;
        }
        __syncthreads();

        #pragma unroll
        for (int kk = 0; kk < 16; kk++) {
            int k0 = kk * 8;
            uint32_t a0 = Ps[r0 * PSP + k0 + tg];
            uint32_t a1 = Ps[r1 * PSP + k0 + tg];
            uint32_t a2 = Ps[r0 * PSP + k0 + tg + 4];
            uint32_t a3 = Ps[r1 * PSP + k0 + tg + 4];
            #pragma unroll
            for (int j = 0; j < 8; j++) {
                uint32_t b0 = Vs[(k0 + tg) * QKP + j * 8 + gi];
                uint32_t b1 = Vs[(k0 + tg + 4) * QKP + j * 8 + gi];
                mma_tf32(o[j], a0, a1, a2, a3, b0, b1);
            }
        }
    }

    float inv0 = 1.f / l0;
    float inv1 = 1.f / l1;
    size_t row0 = (size_t)(b * SEQT + q0 + r0) * DIMV + h * HDIM;
    size_t row1 = (size_t)(b * SEQT + q0 + r1) * DIMV + h * HDIM;
    #pragma unroll
    for (int j = 0; j < 8; j++) {
        int col = j * 8 + 2 * tg;
        *(float2*)&y[row0 + col] = make_float2(o[j][0] * inv0, o[j][1] * inv0);
        *(float2*)&y[row1 + col] = make_float2(o[j][2] * inv1, o[j][3] * inv1);
    }
}

// ---------------------------------------------------------------------------
extern "C" void kernel_launch(void* const* d_in, const int* in_sizes, int n_in,
                              void* d_out, int out_size)
{
    const float* x      = (const float*)d_in[0];
    const float* W_qkv  = (const float*)d_in[1];
    const float* b_qkv  = (const float*)d_in[2];
    const float* W_proj = (const float*)d_in[3];
    const float* b_proj = (const float*)d_in[4];
    float* out = (float*)d_out;

    float* qkv;
    float* yb;
    cudaGetSymbolAddress((void**)&qkv, g_qkv);
    cudaGetSymbolAddress((void**)&yb, g_y);

    // 1) QKV projection (bf16x3 tensor cores)
    {
        dim3 grid(QKV3 / 128, MROWS / 128);
        bf16x3_gemm_bias_kernel<<<grid, 256>>>(x, W_qkv, b_qkv, qkv, MROWS, QKV3, DIMV);
    }

    // 2) Tensor-core flash attention
    {
        int smem_bytes = SMEM_WORDS * 4;
        cudaFuncSetAttribute(flash_attn_tc_kernel,
                             cudaFuncAttributeMaxDynamicSharedMemorySize, smem_bytes);
        dim3 grid(SEQT / BQ, NHEAD, BATCH);
        flash_attn_tc_kernel<<<grid, 256, smem_bytes>>>(qkv, yb);
    }

    // 3) Output projection (bf16x3 tensor cores)
    {
        dim3 grid(DIMV / 128, MROWS / 128);
        bf16x3_gemm_bias_kernel<<<grid, 256>>>(yb, W_proj, b_proj, out, MROWS, DIMV, DIMV);
    }
}

// round 8
// speedup vs baseline: 12.3423x; 1.1097x over previous
#include <cuda_runtime.h>
#include <cuda_bf16.h>
#include <cstdint>

#define DIMV   768
#define QKV3   2304
#define BATCH  8
#define SEQT   1024
#define NHEAD  12
#define HDIM   64
#define MROWS  (BATCH * SEQT)   // 8192

__device__ float g_qkv[(size_t)MROWS * QKV3];   // ~75.5 MB
__device__ float g_y[(size_t)MROWS * DIMV];     // ~25 MB

// ---------------------------------------------------------------------------
// Helpers
// ---------------------------------------------------------------------------
__device__ __forceinline__ uint32_t f2tf(float f) {
    uint32_t u;
    asm("cvt.rna.tf32.f32 %0, %1;" : "=r"(u) : "f"(f));
    return u;
}

__device__ __forceinline__ void mma_tf32(float* d,
                                         uint32_t a0, uint32_t a1, uint32_t a2, uint32_t a3,
                                         uint32_t b0, uint32_t b1)
{
    asm volatile(
        "mma.sync.aligned.m16n8k8.row.col.f32.tf32.tf32.f32 "
        "{%0,%1,%2,%3}, {%4,%5,%6,%7}, {%8,%9}, {%0,%1,%2,%3};\n"
        : "+f"(d[0]), "+f"(d[1]), "+f"(d[2]), "+f"(d[3])
        : "r"(a0), "r"(a1), "r"(a2), "r"(a3), "r"(b0), "r"(b1));
}

__device__ __forceinline__ void mma_bf16(float* d,
                                         uint32_t a0, uint32_t a1, uint32_t a2, uint32_t a3,
                                         uint32_t b0, uint32_t b1)
{
    asm volatile(
        "mma.sync.aligned.m16n8k16.row.col.f32.bf16.bf16.f32 "
        "{%0,%1,%2,%3}, {%4,%5,%6,%7}, {%8,%9}, {%0,%1,%2,%3};\n"
        : "+f"(d[0]), "+f"(d[1]), "+f"(d[2]), "+f"(d[3])
        : "r"(a0), "r"(a1), "r"(a2), "r"(a3), "r"(b0), "r"(b1));
}

// Split two floats (a = lower k index -> low half) into packed bf16 hi/lo words.
__device__ __forceinline__ void split2(float a, float b, uint32_t& h, uint32_t& l)
{
    __nv_bfloat16 ah = __float2bfloat16(a);
    __nv_bfloat16 bh = __float2bfloat16(b);
    h = ((uint32_t)__bfloat16_as_ushort(bh) << 16) | (uint32_t)__bfloat16_as_ushort(ah);
    __nv_bfloat16 al = __float2bfloat16(a - __bfloat162float(ah));
    __nv_bfloat16 bl = __float2bfloat16(b - __bfloat162float(bh));
    l = ((uint32_t)__bfloat16_as_ushort(bl) << 16) | (uint32_t)__bfloat16_as_ushort(al);
}

// ---------------------------------------------------------------------------
// bf16x3 tensor-core GEMM: C[M,N] = A[M,K] @ B[K,N] + bias[N]
// CTA 128x128, BK=16, 8 warps (4M x 2N), warp tile 32x64, mma m16n8k16.
// acc += Ah*Bh + Al*Bh + Ah*Bl.
// ---------------------------------------------------------------------------
#define GBK  16
#define AP   12
#define BP   136

__global__ __launch_bounds__(256, 2)
void bf16x3_gemm_bias_kernel(const float* __restrict__ A,
                             const float* __restrict__ Bm,
                             const float* __restrict__ bias,
                             float* __restrict__ C,
                             int M, int N, int K)
{
    __shared__ uint32_t Ah[128 * AP];
    __shared__ uint32_t Al[128 * AP];
    __shared__ uint32_t Bh[8 * BP];
    __shared__ uint32_t Bl[8 * BP];

    int tid  = threadIdx.x;
    int w    = tid >> 5;
    int lane = tid & 31;
    int gi   = lane >> 2;
    int tg   = lane & 3;
    int wm   = (w & 3) * 32;
    int wn   = (w >> 2) * 64;
    int m0   = blockIdx.y * 128;
    int n0   = blockIdx.x * 128;

    int ar0 = tid >> 2;
    int akc = (tid & 3) * 4;
    int apk = (tid & 3) * 2;
    int bp  = tid >> 5;
    int bnc = (tid & 31) * 4;

    const float* Ap0 = A + (size_t)(m0 + ar0) * K + akc;
    const float* Ap1 = A + (size_t)(m0 + ar0 + 64) * K + akc;
    const float* Bp0 = Bm + (size_t)(2 * bp) * N + n0 + bnc;
    const float* Bp1 = Bm + (size_t)(2 * bp + 1) * N + n0 + bnc;

    float acc[2][8][4];
    #pragma unroll
    for (int mi = 0; mi < 2; mi++)
        #pragma unroll
        for (int nb = 0; nb < 8; nb++)
            #pragma unroll
            for (int e = 0; e < 4; e++) acc[mi][nb][e] = 0.f;

    float4 pa0 = *(const float4*)Ap0;
    float4 pa1 = *(const float4*)Ap1;
    float4 pb0 = *(const float4*)Bp0;
    float4 pb1 = *(const float4*)Bp1;

    for (int k0 = 0; k0 < K; k0 += GBK) {
        {
            uint2 h2, l2;
            split2(pa0.x, pa0.y, h2.x, l2.x);
            split2(pa0.z, pa0.w, h2.y, l2.y);
            *(uint2*)&Ah[ar0 * AP + apk] = h2;
            *(uint2*)&Al[ar0 * AP + apk] = l2;
            split2(pa1.x, pa1.y, h2.x, l2.x);
            split2(pa1.z, pa1.w, h2.y, l2.y);
            *(uint2*)&Ah[(ar0 + 64) * AP + apk] = h2;
            *(uint2*)&Al[(ar0 + 64) * AP + apk] = l2;

            uint4 h4, l4;
            split2(pb0.x, pb1.x, h4.x, l4.x);
            split2(pb0.y, pb1.y, h4.y, l4.y);
            split2(pb0.z, pb1.z, h4.z, l4.z);
            split2(pb0.w, pb1.w, h4.w, l4.w);
            *(uint4*)&Bh[bp * BP + bnc] = h4;
            *(uint4*)&Bl[bp * BP + bnc] = l4;
        }
        __syncthreads();

        if (k0 + GBK < K) {
            Ap0 += GBK; Ap1 += GBK;
            Bp0 += (size_t)GBK * N; Bp1 += (size_t)GBK * N;
            pa0 = *(const float4*)Ap0;
            pa1 = *(const float4*)Ap1;
            pb0 = *(const float4*)Bp0;
            pb1 = *(const float4*)Bp1;
        }

        uint32_t ah[2][4], al[2][4];
        #pragma unroll
        for (int mi = 0; mi < 2; mi++) {
            int r = wm + mi * 16 + gi;
            ah[mi][0] = Ah[r * AP + tg];
            ah[mi][1] = Ah[(r + 8) * AP + tg];
            ah[mi][2] = Ah[r * AP + tg + 4];
            ah[mi][3] = Ah[(r + 8) * AP + tg + 4];
            al[mi][0] = Al[r * AP + tg];
            al[mi][1] = Al[(r + 8) * AP + tg];
            al[mi][2] = Al[r * AP + tg + 4];
            al[mi][3] = Al[(r + 8) * AP + tg + 4];
        }
        #pragma unroll
        for (int nb = 0; nb < 8; nb++) {
            int c = wn + nb * 8 + gi;
            uint32_t bh0 = Bh[tg * BP + c];
            uint32_t bh1 = Bh[(tg + 4) * BP + c];
            uint32_t bl0 = Bl[tg * BP + c];
            uint32_t bl1 = Bl[(tg + 4) * BP + c];
            #pragma unroll
            for (int mi = 0; mi < 2; mi++) {
                mma_bf16(acc[mi][nb], ah[mi][0], ah[mi][1], ah[mi][2], ah[mi][3], bh0, bh1);
                mma_bf16(acc[mi][nb], al[mi][0], al[mi][1], al[mi][2], al[mi][3], bh0, bh1);
                mma_bf16(acc[mi][nb], ah[mi][0], ah[mi][1], ah[mi][2], ah[mi][3], bl0, bl1);
            }
        }
        __syncthreads();
    }

    #pragma unroll
    for (int mi = 0; mi < 2; mi++) {
        int r = m0 + wm + mi * 16 + gi;
        #pragma unroll
        for (int nb = 0; nb < 8; nb++) {
            int c = n0 + wn + nb * 8 + 2 * tg;
            float2 bv = *(const float2*)&bias[c];
            *(float2*)&C[(size_t)r * N + c] =
                make_float2(acc[mi][nb][0] + bv.x, acc[mi][nb][1] + bv.y);
            *(float2*)&C[(size_t)(r + 8) * N + c] =
                make_float2(acc[mi][nb][2] + bv.x, acc[mi][nb][3] + bv.y);
        }
    }
}

// ---------------------------------------------------------------------------
// Flash attention v2:
//   QK in tf32. Softmax in registers.
//   PV via bf16 m16n8k16 with FA2 fragment reuse: the QK C-fragment IS the
//   PV A-fragment (pack s[2kk]/s[2kk+1] pairs to bf16 hi/lo, no shuffles,
//   no smem P round-trip). V stored as packed bf16 hi/lo pairs.
//   3-term compensated: o += Ph*Vh + Pl*Vh + Ph*Vl  (~16-bit P and V).
//   smem 104KB -> 2 CTAs/SM.
// ---------------------------------------------------------------------------
#define BQ     128
#define BKV    128
#define QKP    68
#define VP     72    // pitch for Vh/Vl (banks 8tg+gi -> conflict-free)

#define QS_OFF  0
#define KS_OFF  (QS_OFF + BQ * QKP)          // 8704
#define VH_OFF  (KS_OFF + BKV * QKP)         // 17408
#define VL_OFF  (VH_OFF + (BKV/2) * VP)      // 22016
#define SMEM_WORDS (VL_OFF + (BKV/2) * VP)   // 26624 words = 106496 B

__global__ __launch_bounds__(256, 2)
void flash_attn_tc_kernel(const float* __restrict__ qkv, float* __restrict__ y)
{
    extern __shared__ uint32_t sm[];
    uint32_t* Qs = sm + QS_OFF;
    uint32_t* Ks = sm + KS_OFF;
    uint32_t* Vh = sm + VH_OFF;
    uint32_t* Vl = sm + VL_OFF;

    int tid  = threadIdx.x;
    int w    = tid >> 5;
    int lane = tid & 31;
    int gi   = lane >> 2;
    int tg   = lane & 3;
    int q0   = blockIdx.x * BQ;
    int h    = blockIdx.y;
    int b    = blockIdx.z;
    const float SCALE = 0.125f;

    size_t base = (size_t)b * SEQT * QKV3;
    int qoff = h * HDIM;
    int koff = DIMV + h * HDIM;
    int voff = 2 * DIMV + h * HDIM;

    // Load Q tile -> tf32 smem [128][QKP]
    #pragma unroll
    for (int it = 0; it < 8; it++) {
        int idx = tid + it * 256;
        int r   = idx >> 4;
        int c4  = (idx & 15) * 4;
        float4 v = *(const float4*)&qkv[base + (size_t)(q0 + r) * QKV3 + qoff + c4];
        uint4 t;
        t.x = f2tf(v.x); t.y = f2tf(v.y); t.z = f2tf(v.z); t.w = f2tf(v.w);
        *(uint4*)&Qs[r * QKP + c4] = t;
    }

    int r0 = w * 16 + gi;
    int r1 = r0 + 8;

    float m0 = -1e30f, m1 = -1e30f;
    float l0 = 0.f, l1 = 0.f;
    float o[8][4];
    #pragma unroll
    for (int j = 0; j < 8; j++)
        #pragma unroll
        for (int e = 0; e < 4; e++) o[j][e] = 0.f;

    for (int kv0 = 0; kv0 < SEQT; kv0 += BKV) {
        __syncthreads();   // previous tile's Ks/Vh/Vl readers done

        // K -> tf32 smem
        #pragma unroll
        for (int it = 0; it < 8; it++) {
            int idx = tid + it * 256;
            int r   = idx >> 4;
            int c4  = (idx & 15) * 4;
            size_t row = base + (size_t)(kv0 + r) * QKV3;
            float4 kvv = *(const float4*)&qkv[row + koff + c4];
            uint4 tk;
            tk.x = f2tf(kvv.x); tk.y = f2tf(kvv.y); tk.z = f2tf(kvv.z); tk.w = f2tf(kvv.w);
            *(uint4*)&Ks[r * QKP + c4] = tk;
        }
        // V -> packed bf16 hi/lo pairs: word (kp, n) = {V[2kp][n] lo, V[2kp+1][n] hi}
        #pragma unroll
        for (int it = 0; it < 4; it++) {
            int t   = tid + it * 256;       // 0..1023
            int kp  = t >> 4;               // 0..63
            int c4  = (t & 15) * 4;
            size_t rowa = base + (size_t)(kv0 + 2 * kp) * QKV3 + voff + c4;
            size_t rowb = rowa + QKV3;
            float4 va = *(const float4*)&qkv[rowa];
            float4 vb = *(const float4*)&qkv[rowb];
            uint4 hh, ll;
            split2(va.x, vb.x, hh.x, ll.x);
            split2(va.y, vb.y, hh.y, ll.y);
            split2(va.z, vb.z, hh.z, ll.z);
            split2(va.w, vb.w, hh.w, ll.w);
            *(uint4*)&Vh[kp * VP + c4] = hh;
            *(uint4*)&Vl[kp * VP + c4] = ll;
        }
        __syncthreads();

        // ---- QK: s = Q[16 x 64] @ K^T[64 x 128] (tf32) ----
        float s[16][4];
        #pragma unroll
        for (int j = 0; j < 16; j++)
            #pragma unroll
            for (int e = 0; e < 4; e++) s[j][e] = 0.f;

        #pragma unroll
        for (int kk = 0; kk < 8; kk++) {
            int d0 = kk * 8;
            uint32_t a0 = Qs[r0 * QKP + d0 + tg];
            uint32_t a1 = Qs[r1 * QKP + d0 + tg];
            uint32_t a2 = Qs[r0 * QKP + d0 + tg + 4];
            uint32_t a3 = Qs[r1 * QKP + d0 + tg + 4];
            #pragma unroll
            for (int j = 0; j < 16; j++) {
                uint32_t b0 = Ks[(j * 8 + gi) * QKP + d0 + tg];
                uint32_t b1 = Ks[(j * 8 + gi) * QKP + d0 + tg + 4];
                mma_tf32(s[j], a0, a1, a2, a3, b0, b1);
            }
        }

        // ---- online softmax in registers ----
        float mx0 = -1e30f, mx1 = -1e30f;
        #pragma unroll
        for (int j = 0; j < 16; j++) {
            mx0 = fmaxf(mx0, fmaxf(s[j][0], s[j][1]));
            mx1 = fmaxf(mx1, fmaxf(s[j][2], s[j][3]));
        }
        #pragma unroll
        for (int msk = 1; msk < 4; msk <<= 1) {
            mx0 = fmaxf(mx0, __shfl_xor_sync(0xffffffffu, mx0, msk));
            mx1 = fmaxf(mx1, __shfl_xor_sync(0xffffffffu, mx1, msk));
        }
        float mn0 = fmaxf(m0, mx0 * SCALE);
        float mn1 = fmaxf(m1, mx1 * SCALE);
        float c0 = __expf(m0 - mn0);
        float c1 = __expf(m1 - mn1);

        float sum0 = 0.f, sum1 = 0.f;
        #pragma unroll
        for (int j = 0; j < 16; j++) {
            s[j][0] = __expf(s[j][0] * SCALE - mn0);
            s[j][1] = __expf(s[j][1] * SCALE - mn0);
            s[j][2] = __expf(s[j][2] * SCALE - mn1);
            s[j][3] = __expf(s[j][3] * SCALE - mn1);
            sum0 += s[j][0] + s[j][1];
            sum1 += s[j][2] + s[j][3];
        }
        #pragma unroll
        for (int msk = 1; msk < 4; msk <<= 1) {
            sum0 += __shfl_xor_sync(0xffffffffu, sum0, msk);
            sum1 += __shfl_xor_sync(0xffffffffu, sum1, msk);
        }
        l0 = l0 * c0 + sum0;
        l1 = l1 * c1 + sum1;
        m0 = mn0;
        m1 = mn1;
        #pragma unroll
        for (int j = 0; j < 8; j++) {
            o[j][0] *= c0; o[j][1] *= c0;
            o[j][2] *= c1; o[j][3] *= c1;
        }

        // ---- PV: o += P[16 x 128] @ V[128 x 64] via bf16 fragment reuse ----
        #pragma unroll
        for (int kk = 0; kk < 8; kk++) {
            uint32_t ph[4], pl[4];
            // A-fragment (m16n8k16): a0=P[gi][16kk+2tg..+1], a1=row+8,
            //                        a2=P[gi][16kk+8+2tg..+1], a3=row+8.
            split2(s[2 * kk][0],     s[2 * kk][1],     ph[0], pl[0]);
            split2(s[2 * kk][2],     s[2 * kk][3],     ph[1], pl[1]);
            split2(s[2 * kk + 1][0], s[2 * kk + 1][1], ph[2], pl[2]);
            split2(s[2 * kk + 1][2], s[2 * kk + 1][3], ph[3], pl[3]);
            #pragma unroll
            for (int j = 0; j < 8; j++) {
                int c = j * 8 + gi;
                uint32_t bh0 = Vh[(8 * kk + tg) * VP + c];
                uint32_t bh1 = Vh[(8 * kk + tg + 4) * VP + c];
                uint32_t bl0 = Vl[(8 * kk + tg) * VP + c];
                uint32_t bl1 = Vl[(8 * kk + tg + 4) * VP + c];
                mma_bf16(o[j], ph[0], ph[1], ph[2], ph[3], bh0, bh1);
                mma_bf16(o[j], pl[0], pl[1], pl[2], pl[3], bh0, bh1);
                mma_bf16(o[j], ph[0], ph[1], ph[2], ph[3], bl0, bl1);
            }
        }
    }

    // Epilogue
    float inv0 = 1.f / l0;
    float inv1 = 1.f / l1;
    size_t row0 = (size_t)(b * SEQT + q0 + r0) * DIMV + h * HDIM;
    size_t row1 = (size_t)(b * SEQT + q0 + r1) * DIMV + h * HDIM;
    #pragma unroll
    for (int j = 0; j < 8; j++) {
        int col = j * 8 + 2 * tg;
        *(float2*)&y[row0 + col] = make_float2(o[j][0] * inv0, o[j][1] * inv0);
        *(float2*)&y[row1 + col] = make_float2(o[j][2] * inv1, o[j][3] * inv1);
    }
}

// ---------------------------------------------------------------------------
extern "C" void kernel_launch(void* const* d_in, const int* in_sizes, int n_in,
                              void* d_out, int out_size)
{
    const float* x      = (const float*)d_in[0];
    const float* W_qkv  = (const float*)d_in[1];
    const float* b_qkv  = (const float*)d_in[2];
    const float* W_proj = (const float*)d_in[3];
    const float* b_proj = (const float*)d_in[4];
    float* out = (float*)d_out;

    float* qkv;
    float* yb;
    cudaGetSymbolAddress((void**)&qkv, g_qkv);
    cudaGetSymbolAddress((void**)&yb, g_y);

    // 1) QKV projection (bf16x3 tensor cores)
    {
        dim3 grid(QKV3 / 128, MROWS / 128);
        bf16x3_gemm_bias_kernel<<<grid, 256>>>(x, W_qkv, b_qkv, qkv, MROWS, QKV3, DIMV);
    }

    // 2) Tensor-core flash attention (2 CTAs/SM)
    {
        int smem_bytes = SMEM_WORDS * 4;
        cudaFuncSetAttribute(flash_attn_tc_kernel,
                             cudaFuncAttributeMaxDynamicSharedMemorySize, smem_bytes);
        dim3 grid(SEQT / BQ, NHEAD, BATCH);
        flash_attn_tc_kernel<<<grid, 256, smem_bytes>>>(qkv, yb);
    }

    // 3) Output projection (bf16x3 tensor cores)
    {
        dim3 grid(DIMV / 128, MROWS / 128);
        bf16x3_gemm_bias_kernel<<<grid, 256>>>(yb, W_proj, b_proj, out, MROWS, DIMV, DIMV);
    }
}

// round 9
// speedup vs baseline: 12.6653x; 1.0262x over previous
#include <cuda_runtime.h>
#include <cuda_bf16.h>
#include <cstdint>

#define DIMV   768
#define QKV3   2304
#define BATCH  8
#define SEQT   1024
#define NHEAD  12
#define HDIM   64
#define MROWS  (BATCH * SEQT)   // 8192

__device__ float g_qkv[(size_t)MROWS * QKV3];   // ~75.5 MB
__device__ float g_y[(size_t)MROWS * DIMV];     // ~25 MB

// ---------------------------------------------------------------------------
// Helpers
// ---------------------------------------------------------------------------
__device__ __forceinline__ uint32_t f2tf(float f) {
    uint32_t u;
    asm("cvt.rna.tf32.f32 %0, %1;" : "=r"(u) : "f"(f));
    return u;
}

__device__ __forceinline__ void mma_tf32(float* d,
                                         uint32_t a0, uint32_t a1, uint32_t a2, uint32_t a3,
                                         uint32_t b0, uint32_t b1)
{
    asm volatile(
        "mma.sync.aligned.m16n8k8.row.col.f32.tf32.tf32.f32 "
        "{%0,%1,%2,%3}, {%4,%5,%6,%7}, {%8,%9}, {%0,%1,%2,%3};\n"
        : "+f"(d[0]), "+f"(d[1]), "+f"(d[2]), "+f"(d[3])
        : "r"(a0), "r"(a1), "r"(a2), "r"(a3), "r"(b0), "r"(b1));
}

__device__ __forceinline__ void mma_bf16(float* d,
                                         uint32_t a0, uint32_t a1, uint32_t a2, uint32_t a3,
                                         uint32_t b0, uint32_t b1)
{
    asm volatile(
        "mma.sync.aligned.m16n8k16.row.col.f32.bf16.bf16.f32 "
        "{%0,%1,%2,%3}, {%4,%5,%6,%7}, {%8,%9}, {%0,%1,%2,%3};\n"
        : "+f"(d[0]), "+f"(d[1]), "+f"(d[2]), "+f"(d[3])
        : "r"(a0), "r"(a1), "r"(a2), "r"(a3), "r"(b0), "r"(b1));
}

// Split two floats (a = lower k index -> low half) into packed bf16 hi/lo words.
__device__ __forceinline__ void split2(float a, float b, uint32_t& h, uint32_t& l)
{
    __nv_bfloat16 ah = __float2bfloat16(a);
    __nv_bfloat16 bh = __float2bfloat16(b);
    h = ((uint32_t)__bfloat16_as_ushort(bh) << 16) | (uint32_t)__bfloat16_as_ushort(ah);
    __nv_bfloat16 al = __float2bfloat16(a - __bfloat162float(ah));
    __nv_bfloat16 bl = __float2bfloat16(b - __bfloat162float(bh));
    l = ((uint32_t)__bfloat16_as_ushort(bl) << 16) | (uint32_t)__bfloat16_as_ushort(al);
}

// ---------------------------------------------------------------------------
// bf16x3 tensor-core GEMM, DOUBLE-BUFFERED smem, one sync per k-iter.
// C[M,N] = A[M,K] @ B[K,N] + bias[N]
// CTA 128x128, BK=16, 8 warps (4M x 2N), warp tile 32x64, mma m16n8k16.
// acc += Ah*Bh + Al*Bh + Ah*Bl.
// ---------------------------------------------------------------------------
#define GBK  16
#define AP   12
#define BP   136

__global__ __launch_bounds__(256, 2)
void bf16x3_gemm_bias_kernel(const float* __restrict__ A,
                             const float* __restrict__ Bm,
                             const float* __restrict__ bias,
                             float* __restrict__ C,
                             int M, int N, int K)
{
    __shared__ uint32_t Ah[2][128 * AP];
    __shared__ uint32_t Al[2][128 * AP];
    __shared__ uint32_t Bh[2][8 * BP];
    __shared__ uint32_t Bl[2][8 * BP];

    int tid  = threadIdx.x;
    int w    = tid >> 5;
    int lane = tid & 31;
    int gi   = lane >> 2;
    int tg   = lane & 3;
    int wm   = (w & 3) * 32;
    int wn   = (w >> 2) * 64;
    int m0   = blockIdx.y * 128;
    int n0   = blockIdx.x * 128;

    int ar0 = tid >> 2;
    int akc = (tid & 3) * 4;
    int apk = (tid & 3) * 2;
    int bp  = tid >> 5;
    int bnc = (tid & 31) * 4;

    const float* Ap0 = A + (size_t)(m0 + ar0) * K + akc;
    const float* Ap1 = A + (size_t)(m0 + ar0 + 64) * K + akc;
    const float* Bp0 = Bm + (size_t)(2 * bp) * N + n0 + bnc;
    const float* Bp1 = Bm + (size_t)(2 * bp + 1) * N + n0 + bnc;

    float acc[2][8][4];
    #pragma unroll
    for (int mi = 0; mi < 2; mi++)
        #pragma unroll
        for (int nb = 0; nb < 8; nb++)
            #pragma unroll
            for (int e = 0; e < 4; e++) acc[mi][nb][e] = 0.f;

    // Prologue: load tile 0, convert+store into buffer 0
    {
        float4 pa0 = *(const float4*)Ap0;
        float4 pa1 = *(const float4*)Ap1;
        float4 pb0 = *(const float4*)Bp0;
        float4 pb1 = *(const float4*)Bp1;

        uint2 h2, l2;
        split2(pa0.x, pa0.y, h2.x, l2.x);
        split2(pa0.z, pa0.w, h2.y, l2.y);
        *(uint2*)&Ah[0][ar0 * AP + apk] = h2;
        *(uint2*)&Al[0][ar0 * AP + apk] = l2;
        split2(pa1.x, pa1.y, h2.x, l2.x);
        split2(pa1.z, pa1.w, h2.y, l2.y);
        *(uint2*)&Ah[0][(ar0 + 64) * AP + apk] = h2;
        *(uint2*)&Al[0][(ar0 + 64) * AP + apk] = l2;

        uint4 h4, l4;
        split2(pb0.x, pb1.x, h4.x, l4.x);
        split2(pb0.y, pb1.y, h4.y, l4.y);
        split2(pb0.z, pb1.z, h4.z, l4.z);
        split2(pb0.w, pb1.w, h4.w, l4.w);
        *(uint4*)&Bh[0][bp * BP + bnc] = h4;
        *(uint4*)&Bl[0][bp * BP + bnc] = l4;
    }
    __syncthreads();

    int cur = 0;
    for (int k0 = 0; k0 < K; k0 += GBK) {
        bool has_next = (k0 + GBK < K);
        float4 pa0, pa1, pb0, pb1;
        if (has_next) {
            Ap0 += GBK; Ap1 += GBK;
            Bp0 += (size_t)GBK * N; Bp1 += (size_t)GBK * N;
            pa0 = *(const float4*)Ap0;        // LDGs in flight during mma
            pa1 = *(const float4*)Ap1;
            pb0 = *(const float4*)Bp0;
            pb1 = *(const float4*)Bp1;
        }

        // MMA on buffer cur
        uint32_t ah[2][4], al[2][4];
        #pragma unroll
        for (int mi = 0; mi < 2; mi++) {
            int r = wm + mi * 16 + gi;
            ah[mi][0] = Ah[cur][r * AP + tg];
            ah[mi][1] = Ah[cur][(r + 8) * AP + tg];
            ah[mi][2] = Ah[cur][r * AP + tg + 4];
            ah[mi][3] = Ah[cur][(r + 8) * AP + tg + 4];
            al[mi][0] = Al[cur][r * AP + tg];
            al[mi][1] = Al[cur][(r + 8) * AP + tg];
            al[mi][2] = Al[cur][r * AP + tg + 4];
            al[mi][3] = Al[cur][(r + 8) * AP + tg + 4];
        }
        #pragma unroll
        for (int nb = 0; nb < 8; nb++) {
            int c = wn + nb * 8 + gi;
            uint32_t bh0 = Bh[cur][tg * BP + c];
            uint32_t bh1 = Bh[cur][(tg + 4) * BP + c];
            uint32_t bl0 = Bl[cur][tg * BP + c];
            uint32_t bl1 = Bl[cur][(tg + 4) * BP + c];
            #pragma unroll
            for (int mi = 0; mi < 2; mi++) {
                mma_bf16(acc[mi][nb], ah[mi][0], ah[mi][1], ah[mi][2], ah[mi][3], bh0, bh1);
                mma_bf16(acc[mi][nb], al[mi][0], al[mi][1], al[mi][2], al[mi][3], bh0, bh1);
                mma_bf16(acc[mi][nb], ah[mi][0], ah[mi][1], ah[mi][2], ah[mi][3], bl0, bl1);
            }
        }

        // Convert + store next tile into the other buffer
        if (has_next) {
            int nxt = cur ^ 1;
            uint2 h2, l2;
            split2(pa0.x, pa0.y, h2.x, l2.x);
            split2(pa0.z, pa0.w, h2.y, l2.y);
            *(uint2*)&Ah[nxt][ar0 * AP + apk] = h2;
            *(uint2*)&Al[nxt][ar0 * AP + apk] = l2;
            split2(pa1.x, pa1.y, h2.x, l2.x);
            split2(pa1.z, pa1.w, h2.y, l2.y);
            *(uint2*)&Ah[nxt][(ar0 + 64) * AP + apk] = h2;
            *(uint2*)&Al[nxt][(ar0 + 64) * AP + apk] = l2;

            uint4 h4, l4;
            split2(pb0.x, pb1.x, h4.x, l4.x);
            split2(pb0.y, pb1.y, h4.y, l4.y);
            split2(pb0.z, pb1.z, h4.z, l4.z);
            split2(pb0.w, pb1.w, h4.w, l4.w);
            *(uint4*)&Bh[nxt][bp * BP + bnc] = h4;
            *(uint4*)&Bl[nxt][bp * BP + bnc] = l4;
        }
        __syncthreads();
        cur ^= 1;
    }

    // Epilogue: bias + store
    #pragma unroll
    for (int mi = 0; mi < 2; mi++) {
        int r = m0 + wm + mi * 16 + gi;
        #pragma unroll
        for (int nb = 0; nb < 8; nb++) {
            int c = n0 + wn + nb * 8 + 2 * tg;
            float2 bv = *(const float2*)&bias[c];
            *(float2*)&C[(size_t)r * N + c] =
                make_float2(acc[mi][nb][0] + bv.x, acc[mi][nb][1] + bv.y);
            *(float2*)&C[(size_t)(r + 8) * N + c] =
                make_float2(acc[mi][nb][2] + bv.x, acc[mi][nb][3] + bv.y);
        }
    }
}

// ---------------------------------------------------------------------------
// Flash attention v2 (unchanged from R8):
//   QK tf32, softmax in regs, PV bf16 fragment-reuse 3-term, 2 CTAs/SM.
// ---------------------------------------------------------------------------
#define BQ     128
#define BKV    128
#define QKP    68
#define VP     72

#define QS_OFF  0
#define KS_OFF  (QS_OFF + BQ * QKP)
#define VH_OFF  (KS_OFF + BKV * QKP)
#define VL_OFF  (VH_OFF + (BKV/2) * VP)
#define SMEM_WORDS (VL_OFF + (BKV/2) * VP)

__global__ __launch_bounds__(256, 2)
void flash_attn_tc_kernel(const float* __restrict__ qkv, float* __restrict__ y)
{
    extern __shared__ uint32_t sm[];
    uint32_t* Qs = sm + QS_OFF;
    uint32_t* Ks = sm + KS_OFF;
    uint32_t* Vh = sm + VH_OFF;
    uint32_t* Vl = sm + VL_OFF;

    int tid  = threadIdx.x;
    int w    = tid >> 5;
    int lane = tid & 31;
    int gi   = lane >> 2;
    int tg   = lane & 3;
    int q0   = blockIdx.x * BQ;
    int h    = blockIdx.y;
    int b    = blockIdx.z;
    const float SCALE = 0.125f;

    size_t base = (size_t)b * SEQT * QKV3;
    int qoff = h * HDIM;
    int koff = DIMV + h * HDIM;
    int voff = 2 * DIMV + h * HDIM;

    #pragma unroll
    for (int it = 0; it < 8; it++) {
        int idx = tid + it * 256;
        int r   = idx >> 4;
        int c4  = (idx & 15) * 4;
        float4 v = *(const float4*)&qkv[base + (size_t)(q0 + r) * QKV3 + qoff + c4];
        uint4 t;
        t.x = f2tf(v.x); t.y = f2tf(v.y); t.z = f2tf(v.z); t.w = f2tf(v.w);
        *(uint4*)&Qs[r * QKP + c4] = t;
    }

    int r0 = w * 16 + gi;
    int r1 = r0 + 8;

    float m0 = -1e30f, m1 = -1e30f;
    float l0 = 0.f, l1 = 0.f;
    float o[8][4];
    #pragma unroll
    for (int j = 0; j < 8; j++)
        #pragma unroll
        for (int e = 0; e < 4; e++) o[j][e] = 0.f;

    for (int kv0 = 0; kv0 < SEQT; kv0 += BKV) {
        __syncthreads();

        #pragma unroll
        for (int it = 0; it < 8; it++) {
            int idx = tid + it * 256;
            int r   = idx >> 4;
            int c4  = (idx & 15) * 4;
            size_t row = base + (size_t)(kv0 + r) * QKV3;
            float4 kvv = *(const float4*)&qkv[row + koff + c4];
            uint4 tk;
            tk.x = f2tf(kvv.x); tk.y = f2tf(kvv.y); tk.z = f2tf(kvv.z); tk.w = f2tf(kvv.w);
            *(uint4*)&Ks[r * QKP + c4] = tk;
        }
        #pragma unroll
        for (int it = 0; it < 4; it++) {
            int t   = tid + it * 256;
            int kp  = t >> 4;
            int c4  = (t & 15) * 4;
            size_t rowa = base + (size_t)(kv0 + 2 * kp) * QKV3 + voff + c4;
            size_t rowb = rowa + QKV3;
            float4 va = *(const float4*)&qkv[rowa];
            float4 vb = *(const float4*)&qkv[rowb];
            uint4 hh, ll;
            split2(va.x, vb.x, hh.x, ll.x);
            split2(va.y, vb.y, hh.y, ll.y);
            split2(va.z, vb.z, hh.z, ll.z);
            split2(va.w, vb.w, hh.w, ll.w);
            *(uint4*)&Vh[kp * VP + c4] = hh;
            *(uint4*)&Vl[kp * VP + c4] = ll;
        }
        __syncthreads();

        float s[16][4];
        #pragma unroll
        for (int j = 0; j < 16; j++)
            #pragma unroll
            for (int e = 0; e < 4; e++) s[j][e] = 0.f;

        #pragma unroll
        for (int kk = 0; kk < 8; kk++) {
            int d0 = kk * 8;
            uint32_t a0 = Qs[r0 * QKP + d0 + tg];
            uint32_t a1 = Qs[r1 * QKP + d0 + tg];
            uint32_t a2 = Qs[r0 * QKP + d0 + tg + 4];
            uint32_t a3 = Qs[r1 * QKP + d0 + tg + 4];
            #pragma unroll
            for (int j = 0; j < 16; j++) {
                uint32_t b0 = Ks[(j * 8 + gi) * QKP + d0 + tg];
                uint32_t b1 = Ks[(j * 8 + gi) * QKP + d0 + tg + 4];
                mma_tf32(s[j], a0, a1, a2, a3, b0, b1);
            }
        }

        float mx0 = -1e30f, mx1 = -1e30f;
        #pragma unroll
        for (int j = 0; j < 16; j++) {
            mx0 = fmaxf(mx0, fmaxf(s[j][0], s[j][1]));
            mx1 = fmaxf(mx1, fmaxf(s[j][2], s[j][3]));
        }
        #pragma unroll
        for (int msk = 1; msk < 4; msk <<= 1) {
            mx0 = fmaxf(mx0, __shfl_xor_sync(0xffffffffu, mx0, msk));
            mx1 = fmaxf(mx1, __shfl_xor_sync(0xffffffffu, mx1, msk));
        }
        float mn0 = fmaxf(m0, mx0 * SCALE);
        float mn1 = fmaxf(m1, mx1 * SCALE);
        float c0 = __expf(m0 - mn0);
        float c1 = __expf(m1 - mn1);

        float sum0 = 0.f, sum1 = 0.f;
        #pragma unroll
        for (int j = 0; j < 16; j++) {
            s[j][0] = __expf(s[j][0] * SCALE - mn0);
            s[j][1] = __expf(s[j][1] * SCALE - mn0);
            s[j][2] = __expf(s[j][2] * SCALE - mn1);
            s[j][3] = __expf(s[j][3] * SCALE - mn1);
            sum0 += s[j][0] + s[j][1];
            sum1 += s[j][2] + s[j][3];
        }
        #pragma unroll
        for (int msk = 1; msk < 4; msk <<= 1) {
            sum0 += __shfl_xor_sync(0xffffffffu, sum0, msk);
            sum1 += __shfl_xor_sync(0xffffffffu, sum1, msk);
        }
        l0 = l0 * c0 + sum0;
        l1 = l1 * c1 + sum1;
        m0 = mn0;
        m1 = mn1;
        #pragma unroll
        for (int j = 0; j < 8; j++) {
            o[j][0] *= c0; o[j][1] *= c0;
            o[j][2] *= c1; o[j][3] *= c1;
        }

        #pragma unroll
        for (int kk = 0; kk < 8; kk++) {
            uint32_t ph[4], pl[4];
            split2(s[2 * kk][0],     s[2 * kk][1],     ph[0], pl[0]);
            split2(s[2 * kk][2],     s[2 * kk][3],     ph[1], pl[1]);
            split2(s[2 * kk + 1][0], s[2 * kk + 1][1], ph[2], pl[2]);
            split2(s[2 * kk + 1][2], s[2 * kk + 1][3], ph[3], pl[3]);
            #pragma unroll
            for (int j = 0; j < 8; j++) {
                int c = j * 8 + gi;
                uint32_t bh0 = Vh[(8 * kk + tg) * VP + c];
                uint32_t bh1 = Vh[(8 * kk + tg + 4) * VP + c];
                uint32_t bl0 = Vl[(8 * kk + tg) * VP + c];
                uint32_t bl1 = Vl[(8 * kk + tg + 4) * VP + c];
                mma_bf16(o[j], ph[0], ph[1], ph[2], ph[3], bh0, bh1);
                mma_bf16(o[j], pl[0], pl[1], pl[2], pl[3], bh0, bh1);
                mma_bf16(o[j], ph[0], ph[1], ph[2], ph[3], bl0, bl1);
            }
        }
    }

    float inv0 = 1.f / l0;
    float inv1 = 1.f / l1;
    size_t row0 = (size_t)(b * SEQT + q0 + r0) * DIMV + h * HDIM;
    size_t row1 = (size_t)(b * SEQT + q0 + r1) * DIMV + h * HDIM;
    #pragma unroll
    for (int j = 0; j < 8; j++) {
        int col = j * 8 + 2 * tg;
        *(float2*)&y[row0 + col] = make_float2(o[j][0] * inv0, o[j][1] * inv0);
        *(float2*)&y[row1 + col] = make_float2(o[j][2] * inv1, o[j][3] * inv1);
    }
}

// ---------------------------------------------------------------------------
extern "C" void kernel_launch(void* const* d_in, const int* in_sizes, int n_in,
                              void* d_out, int out_size)
{
    const float* x      = (const float*)d_in[0];
    const float* W_qkv  = (const float*)d_in[1];
    const float* b_qkv  = (const float*)d_in[2];
    const float* W_proj = (const float*)d_in[3];
    const float* b_proj = (const float*)d_in[4];
    float* out = (float*)d_out;

    float* qkv;
    float* yb;
    cudaGetSymbolAddress((void**)&qkv, g_qkv);
    cudaGetSymbolAddress((void**)&yb, g_y);

    // 1) QKV projection (bf16x3 tensor cores, double-buffered)
    {
        dim3 grid(QKV3 / 128, MROWS / 128);
        bf16x3_gemm_bias_kernel<<<grid, 256>>>(x, W_qkv, b_qkv, qkv, MROWS, QKV3, DIMV);
    }

    // 2) Tensor-core flash attention (2 CTAs/SM)
    {
        int smem_bytes = SMEM_WORDS * 4;
        cudaFuncSetAttribute(flash_attn_tc_kernel,
                             cudaFuncAttributeMaxDynamicSharedMemorySize, smem_bytes);
        dim3 grid(SEQT / BQ, NHEAD, BATCH);
        flash_attn_tc_kernel<<<grid, 256, smem_bytes>>>(qkv, yb);
    }

    // 3) Output projection (bf16x3 tensor cores, double-buffered)
    {
        dim3 grid(DIMV / 128, MROWS / 128);
        bf16x3_gemm_bias_kernel<<<grid, 256>>>(yb, W_proj, b_proj, out, MROWS, DIMV, DIMV);
    }
}